// round 4
// baseline (speedup 1.0000x reference)
#include <cuda_runtime.h>
#include <cuda_bf16.h>
#include <math.h>

#define D 256
#define VD 16
#define TM 32          // rows (nodes) per CTA
#define TPAD 36        // padded row length for transposed SMEM tiles
#define CH 64          // edges per shared chunk in edge kernel
#define MAXN 50000
#define MAXE 400000
#define MAXG 256

// ---------------- scratch ----------------
__device__ float g_vn  [MAXN * VD];    // vector-channel norms
__device__ float g_Pd  [MAXN * D];     // node first-layer dst part (incl bm1)
__device__ float g_Qs  [MAXN * D];     // node first-layer src part
__device__ float g_agg [MAXN * D];     // per-node sum of relu(hidden) (deg0 rows stay 0)
__device__ float g_WeF [17 * D];       // We @ Wm1E
__device__ float g_beF [D];
__device__ float g_AP  [23 * D];       // Ws @ Wm1P
__device__ float g_AQ  [23 * D];       // Ws @ Wm1Q
__device__ float g_bP  [D];
__device__ float g_bQ  [D];
__device__ float g_AH  [23 * D];       // Ws @ WnS
__device__ float g_WmF [D * D];        // Wm2 @ WnS
__device__ float g_bH  [D];
__device__ float g_gsum[MAXG * D];
__device__ float g_gcnt[MAXG];
// CSR sort scratch
__device__ int   g_rowcnt[MAXN];
__device__ int   g_roff  [MAXN + 1];
__device__ int   g_cursor[MAXN];
__device__ int   g_esrc  [MAXE];
__device__ int   g_erow  [MAXE];
__device__ float g_es    [MAXE * 20];  // sorted edge_s, padded stride 20 (16B aligned rows)

// ---------------- zero small accumulated buffers ----------------
__global__ void k_zero(int N, int G) {
    int i = blockIdx.x * blockDim.x + threadIdx.x;
    int gd = G * D;
    int total = gd + G + N;
    for (; i < total; i += gridDim.x * blockDim.x) {
        if (i < gd)           g_gsum[i] = 0.f;
        else if (i < gd + G)  g_gcnt[i - gd] = 0.f;
        else                  g_rowcnt[i - gd - G] = 0;
    }
}

// ---------------- histogram of dst ----------------
__global__ void k_hist(const int* __restrict__ edge_index, int E) {
    int i = blockIdx.x * blockDim.x + threadIdx.x;
    if (i < E) atomicAdd(&g_rowcnt[edge_index[E + i]], 1);
}

// ---------------- single-block exclusive scan over rowcnt ----------------
__global__ __launch_bounds__(1024) void k_scan(int N) {
    __shared__ int wsum[32];
    __shared__ int carry_s;
    int tid = threadIdx.x, lane = tid & 31, wid = tid >> 5;
    if (tid == 0) carry_s = 0;
    __syncthreads();
    for (int base = 0; base < N; base += 1024) {
        int idx = base + tid;
        int v = (idx < N) ? g_rowcnt[idx] : 0;
        int inc = v;
        #pragma unroll
        for (int o = 1; o < 32; o <<= 1) {
            int t = __shfl_up_sync(0xFFFFFFFFu, inc, o);
            if (lane >= o) inc += t;
        }
        if (lane == 31) wsum[wid] = inc;
        __syncthreads();
        if (wid == 0) {
            int s = wsum[lane];
            #pragma unroll
            for (int o = 1; o < 32; o <<= 1) {
                int t = __shfl_up_sync(0xFFFFFFFFu, s, o);
                if (lane >= o) s += t;
            }
            wsum[lane] = s;
        }
        __syncthreads();
        int carry = carry_s;
        int excl = carry + (wid ? wsum[wid - 1] : 0) + inc - v;
        if (idx < N) { g_roff[idx] = excl; g_cursor[idx] = excl; }
        __syncthreads();
        if (tid == 0) carry_s = carry + wsum[31];
        __syncthreads();
    }
    if (tid == 0) g_roff[N] = carry_s;
}

// ---------------- scatter edges into sorted (by dst) arrays ----------------
__global__ void k_scatter(const int* __restrict__ edge_index,
                          const float* __restrict__ edge_s, int E) {
    int e = blockIdx.x * blockDim.x + threadIdx.x;
    if (e >= E) return;
    int src = edge_index[e];
    int dst = edge_index[E + e];
    int pos = atomicAdd(&g_cursor[dst], 1);
    g_esrc[pos] = src;
    g_erow[pos] = dst;
    const float* es = edge_s + (long long)e * 17;
    float v[17];
    #pragma unroll
    for (int k = 0; k < 17; k++) v[k] = es[k];
    float4* dst4 = (float4*)&g_es[(long long)pos * 20];
    dst4[0] = make_float4(v[0], v[1], v[2], v[3]);
    dst4[1] = make_float4(v[4], v[5], v[6], v[7]);
    dst4[2] = make_float4(v[8], v[9], v[10], v[11]);
    dst4[3] = make_float4(v[12], v[13], v[14], v[15]);
    g_es[(long long)pos * 20 + 16] = v[16];
}

// ---------------- fold: edge embedding through Wm1 edge block ----------------
__global__ __launch_bounds__(D) void k_wef(const float* __restrict__ We,
                                           const float* __restrict__ be,
                                           const float* __restrict__ Wm1) {
    __shared__ float row[D];
    int j = threadIdx.x, b = blockIdx.x;
    row[j] = (b < 17) ? We[b * D + j] : be[j];
    __syncthreads();
    float a0 = 0.f, a1 = 0.f, a2 = 0.f, a3 = 0.f;
    #pragma unroll 8
    for (int c = 0; c < D; c += 4) {
        a0 += row[c + 0] * Wm1[(528 + c + 0) * D + j];
        a1 += row[c + 1] * Wm1[(528 + c + 1) * D + j];
        a2 += row[c + 2] * Wm1[(528 + c + 2) * D + j];
        a3 += row[c + 3] * Wm1[(528 + c + 3) * D + j];
    }
    float a = (a0 + a1) + (a2 + a3);
    if (b < 17) g_WeF[b * D + j] = a;
    else        g_beF[j] = a;
}

// ---------------- fold: Ws/bs through Wm1 P/Q blocks ----------------
__global__ __launch_bounds__(D) void k_fold2(const float* __restrict__ Ws,
                                             const float* __restrict__ bs,
                                             const float* __restrict__ Wm1,
                                             const float* __restrict__ bm1) {
    __shared__ float row[D];
    int j = threadIdx.x, b = blockIdx.x;
    row[j] = (b < 23) ? Ws[b * D + j] : bs[j];
    __syncthreads();
    float p0 = 0.f, p1 = 0.f, q0 = 0.f, q1 = 0.f;
    #pragma unroll 8
    for (int c = 0; c < D; c += 2) {
        float r0 = row[c], r1 = row[c + 1];
        p0 += r0 * Wm1[(c + 0) * D + j];
        p1 += r1 * Wm1[(c + 1) * D + j];
        q0 += r0 * Wm1[(D + c + 0) * D + j];
        q1 += r1 * Wm1[(D + c + 1) * D + j];
    }
    float aP = p0 + p1, aQ = q0 + q1;
    if (b < 23) { g_AP[b * D + j] = aP; g_AQ[b * D + j] = aQ; }
    else        { g_bP[j] = aP + bm1[j]; g_bQ[j] = aQ; }
}

// ---------------- fold: Wm2@WnS, Ws@WnS, bias ----------------
__global__ __launch_bounds__(D) void k_fold3(const float* __restrict__ Wm2,
                                             const float* __restrict__ bm2,
                                             const float* __restrict__ Ws,
                                             const float* __restrict__ bs,
                                             const float* __restrict__ Wn,
                                             const float* __restrict__ bn) {
    __shared__ float row[D];
    int j = threadIdx.x, b = blockIdx.x;
    if (b < D)            row[j] = Wm2[b * D + j];
    else if (b < D + 23)  row[j] = Ws[(b - D) * D + j];
    else                  row[j] = bs[j] + bm2[j];
    __syncthreads();
    float a0 = 0.f, a1 = 0.f, a2 = 0.f, a3 = 0.f;
    #pragma unroll 8
    for (int c = 0; c < D; c += 4) {
        a0 += row[c + 0] * Wn[(c + 0) * D + j];
        a1 += row[c + 1] * Wn[(c + 1) * D + j];
        a2 += row[c + 2] * Wn[(c + 2) * D + j];
        a3 += row[c + 3] * Wn[(c + 3) * D + j];
    }
    float a = (a0 + a1) + (a2 + a3);
    if (b < D)            g_WmF[b * D + j] = a;
    else if (b < D + 23)  g_AH[(b - D) * D + j] = a;
    else                  g_bH[j] = a + bn[j];
}

// ---------------- node embed + first-layer precompute ----------------
__global__ __launch_bounds__(D) void k_nodeEmb(const float* __restrict__ node_s,
                                               const float* __restrict__ node_v,
                                               const float* __restrict__ Wv,
                                               const float* __restrict__ bv,
                                               const float* __restrict__ Wm1,
                                               int N) {
    __shared__ float ns[TM][24];
    __shared__ float nv[TM][12];
    __shared__ float vnT[VD][TM + 4];
    __shared__ float sWv[4 * VD];
    __shared__ float sbv[VD];
    int j = threadIdx.x;
    int n0 = blockIdx.x * TM;
    int nvld = min(TM, N - n0);

    for (int i = j; i < nvld * 23; i += D) ns[i / 23][i % 23] = node_s[n0 * 23 + i];
    for (int i = j; i < nvld * 12; i += D) nv[i / 12][i % 12] = node_v[n0 * 12 + i];
    if (j < 4 * VD) sWv[j] = Wv[j];
    if (j < VD) sbv[j] = bv[j];
    __syncthreads();

    for (int idx = j; idx < TM * VD; idx += D) {
        int r = idx / VD, o = idx % VD;
        float val = 0.f;
        if (r < nvld) {
            float x = sbv[o], y = sbv[o], z = sbv[o];
            #pragma unroll
            for (int k = 0; k < 4; k++) {
                float w = sWv[k * VD + o];
                x += nv[r][k * 3 + 0] * w;
                y += nv[r][k * 3 + 1] * w;
                z += nv[r][k * 3 + 2] * w;
            }
            val = sqrtf(x * x + y * y + z * z);
            g_vn[(n0 + r) * VD + o] = val;
        }
        vnT[o][r] = val;
    }
    __syncthreads();

    float accP[TM], accQ[TM];
    float bp = g_bP[j], bq = g_bQ[j];
    #pragma unroll
    for (int r = 0; r < TM; r++) { accP[r] = bp; accQ[r] = bq; }

    #pragma unroll 4
    for (int k = 0; k < 23; k++) {
        float wP = __ldg(&g_AP[k * D + j]);
        float wQ = __ldg(&g_AQ[k * D + j]);
        #pragma unroll
        for (int r = 0; r < TM; r++) {
            float a = ns[r][k];
            accP[r] += a * wP;
            accQ[r] += a * wQ;
        }
    }
    const float* W1V = Wm1 + 512 * D;
    #pragma unroll 4
    for (int k = 0; k < VD; k++) {
        float wV = __ldg(&W1V[k * D + j]);
        #pragma unroll
        for (int r = 0; r < TM; r++) accQ[r] += vnT[k][r] * wV;
    }
    for (int r = 0; r < nvld; r++) {
        g_Pd[(n0 + r) * D + j] = accP[r];
        g_Qs[(n0 + r) * D + j] = accQ[r];
    }
}

// ---------------- edge kernel (CSR, no atomics) ----------------
__global__ __launch_bounds__(D) void k_edgeCSR(int N) {
    __shared__ float sPd[TM * D];          // 32 KB
    __shared__ float sEs[CH][20];          // 5.1 KB
    __shared__ int   sSrc[CH];
    __shared__ int   sRow[CH];
    int j = threadIdx.x;
    int n0 = blockIdx.x * TM;
    int nvld = min(TM, N - n0);

    for (int i = j; i < nvld * D; i += D) {
        int r = i >> 8, k = i & 255;
        sPd[r * D + k] = g_Pd[(n0 + r) * D + k];
    }
    int e0 = g_roff[n0];
    int e1 = g_roff[n0 + nvld];

    float wf[17];
    #pragma unroll
    for (int k = 0; k < 17; k++) wf[k] = g_WeF[k * D + j];
    float bef = g_beF[j];

    int cur = -1;
    float a = 0.f, pd = 0.f;

    for (int base = e0; base < e1; base += CH) {
        int cnt = min(CH, e1 - base);
        __syncthreads();
        for (int t = j; t < cnt * 20; t += D)
            sEs[t / 20][t % 20] = g_es[(long long)base * 20 + t];
        for (int t = j; t < cnt; t += D) {
            sSrc[t] = g_esrc[base + t];
            sRow[t] = g_erow[base + t] - n0;
        }
        __syncthreads();

        float q = __ldg(&g_Qs[sSrc[0] * D + j]);
        for (int i = 0; i < cnt; i++) {
            float qn = (i + 1 < cnt) ? __ldg(&g_Qs[sSrc[i + 1] * D + j]) : 0.f;
            int r = sRow[i];
            if (r != cur) {
                if (cur >= 0) g_agg[(n0 + cur) * D + j] = a;
                cur = r; a = 0.f;
                pd = sPd[r * D + j];
            }
            const float4* ep = (const float4*)sEs[i];
            float4 x0 = ep[0], x1 = ep[1], x2 = ep[2], x3 = ep[3];
            float e16 = sEs[i][16];
            float h = bef + pd + q;
            h = fmaf(x0.x, wf[0],  h); h = fmaf(x0.y, wf[1],  h);
            h = fmaf(x0.z, wf[2],  h); h = fmaf(x0.w, wf[3],  h);
            h = fmaf(x1.x, wf[4],  h); h = fmaf(x1.y, wf[5],  h);
            h = fmaf(x1.z, wf[6],  h); h = fmaf(x1.w, wf[7],  h);
            h = fmaf(x2.x, wf[8],  h); h = fmaf(x2.y, wf[9],  h);
            h = fmaf(x2.z, wf[10], h); h = fmaf(x2.w, wf[11], h);
            h = fmaf(x3.x, wf[12], h); h = fmaf(x3.y, wf[13], h);
            h = fmaf(x3.z, wf[14], h); h = fmaf(x3.w, wf[15], h);
            h = fmaf(e16,  wf[16], h);
            a += fmaxf(h, 0.f);
            q = qn;
        }
    }
    if (cur >= 0) g_agg[(n0 + cur) * D + j] = a;
}

// ---------------- node output: folded GEMMs + LayerNorm + ReLU + pooling ----------------
__global__ __launch_bounds__(D) void k_node2(const float* __restrict__ node_s,
                                             const float* __restrict__ Wn,
                                             const float* __restrict__ gamma,
                                             const float* __restrict__ beta,
                                             const int* __restrict__ batch,
                                             int N) {
    __shared__ float aT[D * TPAD];
    __shared__ float ns2[TM][24];
    __shared__ float vnT[VD][TPAD];
    __shared__ float rc[TM];
    __shared__ float red[2][TM];
    __shared__ int sb[TM];
    int j = threadIdx.x;
    int n0 = blockIdx.x * TM;
    int nvld = min(TM, N - n0);

    if (j < TM) {
        float deg = 0.f;
        if (j < nvld) {
            int n = n0 + j;
            deg = (float)(g_roff[n + 1] - g_roff[n]);
            sb[j] = batch[n];
        } else sb[j] = 0;
        rc[j] = 1.f / fmaxf(deg, 1.f);
    }
    for (int i = j; i < nvld * 23; i += D) ns2[i / 23][i % 23] = node_s[n0 * 23 + i];
    for (int i = j; i < TM * VD; i += D) {
        int r = i / VD, k = i % VD;
        vnT[k][r] = (r < nvld) ? g_vn[(n0 + r) * VD + k] : 0.f;
    }
    __syncthreads();
    for (int i = j; i < TM * D; i += D) {
        int r = i >> 8, k = i & 255;
        aT[k * TPAD + r] = (r < nvld) ? g_agg[(n0 + r) * D + k] * rc[r] : 0.f;
    }
    __syncthreads();

    float acc[TM];
    float bh = g_bH[j];
    #pragma unroll
    for (int r = 0; r < TM; r++) acc[r] = bh;

    #pragma unroll 4
    for (int k = 0; k < 23; k++) {
        float w = __ldg(&g_AH[k * D + j]);
        #pragma unroll
        for (int r = 0; r < TM; r++) acc[r] += ns2[r][k] * w;
    }
    const float* WnV = Wn + D * D;
    #pragma unroll 4
    for (int k = 0; k < VD; k++) {
        float w = __ldg(&WnV[k * D + j]);
        const float4* row = (const float4*)&vnT[k][0];
        #pragma unroll
        for (int r4 = 0; r4 < TM / 4; r4++) {
            float4 a = row[r4];
            acc[4*r4+0] += a.x * w; acc[4*r4+1] += a.y * w;
            acc[4*r4+2] += a.z * w; acc[4*r4+3] += a.w * w;
        }
    }
    #pragma unroll 2
    for (int k = 0; k < D; k += 4) {
        float w0 = __ldg(&g_WmF[(k + 0) * D + j]);
        float w1 = __ldg(&g_WmF[(k + 1) * D + j]);
        float w2 = __ldg(&g_WmF[(k + 2) * D + j]);
        float w3 = __ldg(&g_WmF[(k + 3) * D + j]);
        const float4* r0 = (const float4*)&aT[(k + 0) * TPAD];
        const float4* r1 = (const float4*)&aT[(k + 1) * TPAD];
        const float4* r2 = (const float4*)&aT[(k + 2) * TPAD];
        const float4* r3 = (const float4*)&aT[(k + 3) * TPAD];
        #pragma unroll
        for (int r4 = 0; r4 < TM / 4; r4++) {
            float4 a0 = r0[r4], a1 = r1[r4], a2 = r2[r4], a3 = r3[r4];
            acc[4*r4+0] += a0.x * w0 + a1.x * w1 + a2.x * w2 + a3.x * w3;
            acc[4*r4+1] += a0.y * w0 + a1.y * w1 + a2.y * w2 + a3.y * w3;
            acc[4*r4+2] += a0.z * w0 + a1.z * w1 + a2.z * w2 + a3.z * w3;
            acc[4*r4+3] += a0.w * w0 + a1.w * w1 + a2.w * w2 + a3.w * w3;
        }
    }
    __syncthreads();
    float* hS = aT;
    #pragma unroll
    for (int r = 0; r < TM; r++) hS[r * D + j] = acc[r];
    __syncthreads();

    int wid = j >> 5, lane = j & 31;
    for (int r = wid; r < TM; r += 8) {
        float s1 = 0.f, s2 = 0.f;
        #pragma unroll
        for (int c = lane; c < D; c += 32) { float x = hS[r * D + c]; s1 += x; s2 += x * x; }
        #pragma unroll
        for (int o = 16; o; o >>= 1) {
            s1 += __shfl_xor_sync(0xFFFFFFFFu, s1, o);
            s2 += __shfl_xor_sync(0xFFFFFFFFu, s2, o);
        }
        if (lane == 0) {
            float mu = s1 * (1.f / D);
            float var = s2 * (1.f / D) - mu * mu;
            red[0][r] = mu;
            red[1][r] = rsqrtf(var + 1e-5f);
        }
    }
    __syncthreads();

    float ga = gamma[j], be = beta[j];
    for (int r = 0; r < nvld; r++) {
        float v = (acc[r] - red[0][r]) * red[1][r] * ga + be;
        v = fmaxf(v, 0.f);
        atomicAdd(&g_gsum[sb[r] * D + j], v);
    }
    if (j < nvld) atomicAdd(&g_gcnt[sb[j]], 1.f);
}

// ---------------- final: divide pooled sums ----------------
__global__ __launch_bounds__(D) void k_final(float* __restrict__ out, int G) {
    int g = blockIdx.x, j = threadIdx.x;
    out[g * D + j] = g_gsum[g * D + j] / fmaxf(g_gcnt[g], 1.f);
}

// ---------------- launch ----------------
extern "C" void kernel_launch(void* const* d_in, const int* in_sizes, int n_in,
                              void* d_out, int out_size) {
    const float* node_s = (const float*)d_in[0];
    const float* node_v = (const float*)d_in[1];
    const float* edge_s = (const float*)d_in[2];
    const int*   edge_index = (const int*)d_in[3];
    const int*   batch  = (const int*)d_in[4];
    const float* Ws  = (const float*)d_in[5];
    const float* bs  = (const float*)d_in[6];
    const float* Wv  = (const float*)d_in[7];
    const float* bv  = (const float*)d_in[8];
    const float* We  = (const float*)d_in[9];
    const float* be  = (const float*)d_in[10];
    const float* Wm1 = (const float*)d_in[11];
    const float* bm1 = (const float*)d_in[12];
    const float* Wm2 = (const float*)d_in[13];
    const float* bm2 = (const float*)d_in[14];
    const float* Wn  = (const float*)d_in[15];
    const float* bn  = (const float*)d_in[16];
    const float* gamma = (const float*)d_in[17];
    const float* beta  = (const float*)d_in[18];

    int N = in_sizes[0] / 23;
    int E = in_sizes[2] / 17;
    int G = out_size / D;

    k_zero<<<256, 256>>>(N, G);
    k_hist<<<(E + 255) / 256, 256>>>(edge_index, E);
    k_wef<<<18, D>>>(We, be, Wm1);
    k_fold2<<<24, D>>>(Ws, bs, Wm1, bm1);
    k_fold3<<<D + 24, D>>>(Wm2, bm2, Ws, bs, Wn, bn);
    k_scan<<<1, 1024>>>(N);
    k_scatter<<<(E + 255) / 256, 256>>>(edge_index, edge_s, E);
    k_nodeEmb<<<(N + TM - 1) / TM, D>>>(node_s, node_v, Wv, bv, Wm1, N);
    k_edgeCSR<<<(N + TM - 1) / TM, D>>>(N);
    k_node2<<<(N + TM - 1) / TM, D>>>(node_s, Wn, gamma, beta, batch, N);
    k_final<<<G, D>>>((float*)d_out, G);
}

// round 6
// speedup vs baseline: 1.4013x; 1.4013x over previous
#include <cuda_runtime.h>
#include <cuda_bf16.h>
#include <math.h>

#define D 256
#define VD 16
#define TM 32          // rows (nodes) per CTA
#define TPAD 36        // padded row length for transposed SMEM tiles
#define CH 128         // edges per shared chunk in edge kernel
#define PF 4           // Qs prefetch depth
#define MAXN 50000
#define MAXE 400000
#define MAXG 256

// ---------------- scratch ----------------
__device__ float g_vn  [MAXN * VD];    // vector-channel norms
__device__ float g_Pd  [MAXN * D];     // node first-layer dst part (incl bm1)
__device__ float g_Qs  [MAXN * D];     // node first-layer src part
__device__ float g_agg [MAXN * D];     // per-node sum of relu(hidden) (deg0 rows stay 0)
__device__ float g_WeF [17 * D];       // We @ Wm1E
__device__ float g_beF [D];
__device__ float g_AP  [23 * D];       // Ws @ Wm1P
__device__ float g_AQ  [23 * D];       // Ws @ Wm1Q
__device__ float g_bP  [D];
__device__ float g_bQ  [D];
__device__ float g_AH  [23 * D];       // Ws @ WnS
__device__ float g_WmF [D * D];        // Wm2 @ WnS
__device__ float g_bH  [D];
__device__ float g_gsum[MAXG * D];
__device__ float g_gcnt[MAXG];
// CSR sort scratch
__device__ int   g_rowcnt[MAXN];
__device__ int   g_roff  [MAXN + 1];
__device__ int   g_cursor[MAXN];
__device__ int   g_esrc  [MAXE];
__device__ int   g_erow  [MAXE];
__device__ float g_es    [MAXE * 20];  // sorted edge_s, padded stride 20 (16B aligned rows)

// ---------------- zero small accumulated buffers ----------------
__global__ void k_zero(int N, int G) {
    int i = blockIdx.x * blockDim.x + threadIdx.x;
    int gd = G * D;
    int total = gd + G + N;
    for (; i < total; i += gridDim.x * blockDim.x) {
        if (i < gd)           g_gsum[i] = 0.f;
        else if (i < gd + G)  g_gcnt[i - gd] = 0.f;
        else                  g_rowcnt[i - gd - G] = 0;
    }
}

// ---------------- histogram of dst ----------------
__global__ void k_hist(const int* __restrict__ edge_index, int E) {
    int i = blockIdx.x * blockDim.x + threadIdx.x;
    if (i < E) atomicAdd(&g_rowcnt[edge_index[E + i]], 1);
}

// ---------------- single-block exclusive scan over rowcnt ----------------
__global__ __launch_bounds__(1024) void k_scan(int N) {
    __shared__ int wsum[32];
    __shared__ int carry_s;
    int tid = threadIdx.x, lane = tid & 31, wid = tid >> 5;
    if (tid == 0) carry_s = 0;
    __syncthreads();
    for (int base = 0; base < N; base += 1024) {
        int idx = base + tid;
        int v = (idx < N) ? g_rowcnt[idx] : 0;
        int inc = v;
        #pragma unroll
        for (int o = 1; o < 32; o <<= 1) {
            int t = __shfl_up_sync(0xFFFFFFFFu, inc, o);
            if (lane >= o) inc += t;
        }
        if (lane == 31) wsum[wid] = inc;
        __syncthreads();
        if (wid == 0) {
            int s = wsum[lane];
            #pragma unroll
            for (int o = 1; o < 32; o <<= 1) {
                int t = __shfl_up_sync(0xFFFFFFFFu, s, o);
                if (lane >= o) s += t;
            }
            wsum[lane] = s;
        }
        __syncthreads();
        int carry = carry_s;
        int excl = carry + (wid ? wsum[wid - 1] : 0) + inc - v;
        if (idx < N) { g_roff[idx] = excl; g_cursor[idx] = excl; }
        __syncthreads();
        if (tid == 0) carry_s = carry + wsum[31];
        __syncthreads();
    }
    if (tid == 0) g_roff[N] = carry_s;
}

// ---------------- scatter edges into sorted (by dst) arrays ----------------
__global__ void k_scatter(const int* __restrict__ edge_index,
                          const float* __restrict__ edge_s, int E) {
    int e = blockIdx.x * blockDim.x + threadIdx.x;
    if (e >= E) return;
    int src = edge_index[e];
    int dst = edge_index[E + e];
    int pos = atomicAdd(&g_cursor[dst], 1);
    g_esrc[pos] = src;
    g_erow[pos] = dst;
    const float* es = edge_s + (long long)e * 17;
    float v[17];
    #pragma unroll
    for (int k = 0; k < 17; k++) v[k] = es[k];
    float4* dst4 = (float4*)&g_es[(long long)pos * 20];
    dst4[0] = make_float4(v[0], v[1], v[2], v[3]);
    dst4[1] = make_float4(v[4], v[5], v[6], v[7]);
    dst4[2] = make_float4(v[8], v[9], v[10], v[11]);
    dst4[3] = make_float4(v[12], v[13], v[14], v[15]);
    g_es[(long long)pos * 20 + 16] = v[16];
}

// ---------------- fold: edge embedding through Wm1 edge block ----------------
__global__ __launch_bounds__(D) void k_wef(const float* __restrict__ We,
                                           const float* __restrict__ be,
                                           const float* __restrict__ Wm1) {
    __shared__ float row[D];
    int j = threadIdx.x, b = blockIdx.x;
    row[j] = (b < 17) ? We[b * D + j] : be[j];
    __syncthreads();
    float a0 = 0.f, a1 = 0.f, a2 = 0.f, a3 = 0.f;
    #pragma unroll 8
    for (int c = 0; c < D; c += 4) {
        a0 += row[c + 0] * Wm1[(528 + c + 0) * D + j];
        a1 += row[c + 1] * Wm1[(528 + c + 1) * D + j];
        a2 += row[c + 2] * Wm1[(528 + c + 2) * D + j];
        a3 += row[c + 3] * Wm1[(528 + c + 3) * D + j];
    }
    float a = (a0 + a1) + (a2 + a3);
    if (b < 17) g_WeF[b * D + j] = a;
    else        g_beF[j] = a;
}

// ---------------- fold: Ws/bs through Wm1 P/Q blocks ----------------
__global__ __launch_bounds__(D) void k_fold2(const float* __restrict__ Ws,
                                             const float* __restrict__ bs,
                                             const float* __restrict__ Wm1,
                                             const float* __restrict__ bm1) {
    __shared__ float row[D];
    int j = threadIdx.x, b = blockIdx.x;
    row[j] = (b < 23) ? Ws[b * D + j] : bs[j];
    __syncthreads();
    float p0 = 0.f, p1 = 0.f, q0 = 0.f, q1 = 0.f;
    #pragma unroll 8
    for (int c = 0; c < D; c += 2) {
        float r0 = row[c], r1 = row[c + 1];
        p0 += r0 * Wm1[(c + 0) * D + j];
        p1 += r1 * Wm1[(c + 1) * D + j];
        q0 += r0 * Wm1[(D + c + 0) * D + j];
        q1 += r1 * Wm1[(D + c + 1) * D + j];
    }
    float aP = p0 + p1, aQ = q0 + q1;
    if (b < 23) { g_AP[b * D + j] = aP; g_AQ[b * D + j] = aQ; }
    else        { g_bP[j] = aP + bm1[j]; g_bQ[j] = aQ; }
}

// ---------------- fold: Wm2@WnS, Ws@WnS, bias ----------------
__global__ __launch_bounds__(D) void k_fold3(const float* __restrict__ Wm2,
                                             const float* __restrict__ bm2,
                                             const float* __restrict__ Ws,
                                             const float* __restrict__ bs,
                                             const float* __restrict__ Wn,
                                             const float* __restrict__ bn) {
    __shared__ float row[D];
    int j = threadIdx.x, b = blockIdx.x;
    if (b < D)            row[j] = Wm2[b * D + j];
    else if (b < D + 23)  row[j] = Ws[(b - D) * D + j];
    else                  row[j] = bs[j] + bm2[j];
    __syncthreads();
    float a0 = 0.f, a1 = 0.f, a2 = 0.f, a3 = 0.f;
    #pragma unroll 8
    for (int c = 0; c < D; c += 4) {
        a0 += row[c + 0] * Wn[(c + 0) * D + j];
        a1 += row[c + 1] * Wn[(c + 1) * D + j];
        a2 += row[c + 2] * Wn[(c + 2) * D + j];
        a3 += row[c + 3] * Wn[(c + 3) * D + j];
    }
    float a = (a0 + a1) + (a2 + a3);
    if (b < D)            g_WmF[b * D + j] = a;
    else if (b < D + 23)  g_AH[(b - D) * D + j] = a;
    else                  g_bH[j] = a + bn[j];
}

// ---------------- node embed + first-layer precompute ----------------
__global__ __launch_bounds__(D) void k_nodeEmb(const float* __restrict__ node_s,
                                               const float* __restrict__ node_v,
                                               const float* __restrict__ Wv,
                                               const float* __restrict__ bv,
                                               const float* __restrict__ Wm1,
                                               int N) {
    __shared__ float ns[TM][24];
    __shared__ float nv[TM][12];
    __shared__ float vnT[VD][TM + 4];
    __shared__ float sWv[4 * VD];
    __shared__ float sbv[VD];
    int j = threadIdx.x;
    int n0 = blockIdx.x * TM;
    int nvld = min(TM, N - n0);

    for (int i = j; i < nvld * 23; i += D) ns[i / 23][i % 23] = node_s[n0 * 23 + i];
    for (int i = j; i < nvld * 12; i += D) nv[i / 12][i % 12] = node_v[n0 * 12 + i];
    if (j < 4 * VD) sWv[j] = Wv[j];
    if (j < VD) sbv[j] = bv[j];
    __syncthreads();

    for (int idx = j; idx < TM * VD; idx += D) {
        int r = idx / VD, o = idx % VD;
        float val = 0.f;
        if (r < nvld) {
            float x = sbv[o], y = sbv[o], z = sbv[o];
            #pragma unroll
            for (int k = 0; k < 4; k++) {
                float w = sWv[k * VD + o];
                x += nv[r][k * 3 + 0] * w;
                y += nv[r][k * 3 + 1] * w;
                z += nv[r][k * 3 + 2] * w;
            }
            val = sqrtf(x * x + y * y + z * z);
            g_vn[(n0 + r) * VD + o] = val;
        }
        vnT[o][r] = val;
    }
    __syncthreads();

    float accP[TM], accQ[TM];
    float bp = g_bP[j], bq = g_bQ[j];
    #pragma unroll
    for (int r = 0; r < TM; r++) { accP[r] = bp; accQ[r] = bq; }

    float wP = __ldg(&g_AP[j]), wQ = __ldg(&g_AQ[j]);
    for (int k = 0; k < 23; k++) {
        float wPn = 0.f, wQn = 0.f;
        if (k + 1 < 23) { wPn = __ldg(&g_AP[(k + 1) * D + j]); wQn = __ldg(&g_AQ[(k + 1) * D + j]); }
        #pragma unroll
        for (int r = 0; r < TM; r++) {
            float a = ns[r][k];
            accP[r] += a * wP;
            accQ[r] += a * wQ;
        }
        wP = wPn; wQ = wQn;
    }
    const float* W1V = Wm1 + 512 * D;
    #pragma unroll 4
    for (int k = 0; k < VD; k++) {
        float wV = __ldg(&W1V[k * D + j]);
        #pragma unroll
        for (int r = 0; r < TM; r++) accQ[r] += vnT[k][r] * wV;
    }
    for (int r = 0; r < nvld; r++) {
        g_Pd[(n0 + r) * D + j] = accP[r];
        g_Qs[(n0 + r) * D + j] = accQ[r];
    }
}

// ---------------- edge kernel (CSR, no atomics, PF-deep Qs prefetch) ----------------
__global__ __launch_bounds__(D) void k_edgeCSR(int N) {
    __shared__ float sPd[TM * D];          // 32 KB
    __shared__ float sEs[CH][20];          // 10.2 KB
    __shared__ int   sSrc[CH];
    __shared__ int   sRow[CH];
    int j = threadIdx.x;
    int n0 = blockIdx.x * TM;
    int nvld = min(TM, N - n0);

    for (int i = j; i < nvld * D; i += D) {
        int r = i >> 8, k = i & 255;
        sPd[r * D + k] = g_Pd[(n0 + r) * D + k];
    }
    int e0 = g_roff[n0];
    int e1 = g_roff[n0 + nvld];

    float wf[17];
    #pragma unroll
    for (int k = 0; k < 17; k++) wf[k] = g_WeF[k * D + j];
    float bef = g_beF[j];

    int cur = -1;
    float a = 0.f, bpd = 0.f;

    for (int base = e0; base < e1; base += CH) {
        int cnt = min(CH, e1 - base);
        __syncthreads();
        for (int t = j; t < cnt * 20; t += D)
            sEs[t / 20][t % 20] = g_es[(long long)base * 20 + t];
        for (int t = j; t < cnt; t += D) {
            sSrc[t] = g_esrc[base + t];
            sRow[t] = g_erow[base + t] - n0;
        }
        __syncthreads();

        float q[PF];
        #pragma unroll
        for (int p = 0; p < PF; p++)
            q[p] = (p < cnt) ? __ldg(&g_Qs[sSrc[p] * D + j]) : 0.f;

        for (int i = 0; i < cnt; i += PF) {
            #pragma unroll
            for (int u = 0; u < PF; u++) {
                int idx = i + u;
                if (idx >= cnt) break;
                float qc = q[u];
                int nidx = idx + PF;
                q[u] = (nidx < cnt) ? __ldg(&g_Qs[sSrc[nidx] * D + j]) : 0.f;
                int r = sRow[idx];
                if (r != cur) {
                    if (cur >= 0) g_agg[(n0 + cur) * D + j] = a;
                    cur = r; a = 0.f;
                    bpd = bef + sPd[r * D + j];
                }
                const float4* ep = (const float4*)sEs[idx];
                float4 x0 = ep[0], x1 = ep[1], x2 = ep[2], x3 = ep[3];
                float h = bpd + qc;
                h = fmaf(sEs[idx][16], wf[16], h);
                h = fmaf(x0.x, wf[0],  h); h = fmaf(x0.y, wf[1],  h);
                h = fmaf(x0.z, wf[2],  h); h = fmaf(x0.w, wf[3],  h);
                h = fmaf(x1.x, wf[4],  h); h = fmaf(x1.y, wf[5],  h);
                h = fmaf(x1.z, wf[6],  h); h = fmaf(x1.w, wf[7],  h);
                h = fmaf(x2.x, wf[8],  h); h = fmaf(x2.y, wf[9],  h);
                h = fmaf(x2.z, wf[10], h); h = fmaf(x2.w, wf[11], h);
                h = fmaf(x3.x, wf[12], h); h = fmaf(x3.y, wf[13], h);
                h = fmaf(x3.z, wf[14], h); h = fmaf(x3.w, wf[15], h);
                a += fmaxf(h, 0.f);
            }
        }
    }
    if (cur >= 0) g_agg[(n0 + cur) * D + j] = a;
}

// ---------------- node output: folded GEMMs + LayerNorm + ReLU + pooling ----------------
__global__ __launch_bounds__(D) void k_node2(const float* __restrict__ node_s,
                                             const float* __restrict__ Wn,
                                             const float* __restrict__ gamma,
                                             const float* __restrict__ beta,
                                             const int* __restrict__ batch,
                                             int N) {
    __shared__ float aT[D * TPAD];
    __shared__ float ns2[TM][24];
    __shared__ float vnT[VD][TPAD];
    __shared__ float rc[TM];
    __shared__ float red[2][TM];
    __shared__ int sb[TM];
    int j = threadIdx.x;
    int n0 = blockIdx.x * TM;
    int nvld = min(TM, N - n0);

    if (j < TM) {
        float deg = 0.f;
        if (j < nvld) {
            int n = n0 + j;
            deg = (float)(g_roff[n + 1] - g_roff[n]);
            sb[j] = batch[n];
        } else sb[j] = 0;
        rc[j] = 1.f / fmaxf(deg, 1.f);
    }
    for (int i = j; i < nvld * 23; i += D) ns2[i / 23][i % 23] = node_s[n0 * 23 + i];
    for (int i = j; i < TM * VD; i += D) {
        int r = i / VD, k = i % VD;
        vnT[k][r] = (r < nvld) ? g_vn[(n0 + r) * VD + k] : 0.f;
    }
    __syncthreads();
    for (int i = j; i < TM * D; i += D) {
        int r = i >> 8, k = i & 255;
        aT[k * TPAD + r] = (r < nvld) ? g_agg[(n0 + r) * D + k] * rc[r] : 0.f;
    }
    __syncthreads();

    float acc[TM];
    float bh = g_bH[j];
    #pragma unroll
    for (int r = 0; r < TM; r++) acc[r] = bh;

    #pragma unroll 4
    for (int k = 0; k < 23; k++) {
        float w = __ldg(&g_AH[k * D + j]);
        #pragma unroll
        for (int r = 0; r < TM; r++) acc[r] += ns2[r][k] * w;
    }
    const float* WnV = Wn + D * D;
    #pragma unroll 4
    for (int k = 0; k < VD; k++) {
        float w = __ldg(&WnV[k * D + j]);
        const float4* row = (const float4*)&vnT[k][0];
        #pragma unroll
        for (int r4 = 0; r4 < TM / 4; r4++) {
            float4 a = row[r4];
            acc[4*r4+0] += a.x * w; acc[4*r4+1] += a.y * w;
            acc[4*r4+2] += a.z * w; acc[4*r4+3] += a.w * w;
        }
    }
    // double-buffered 256-K GEMM over g_WmF
    {
        float w0 = __ldg(&g_WmF[0 * D + j]);
        float w1 = __ldg(&g_WmF[1 * D + j]);
        float w2 = __ldg(&g_WmF[2 * D + j]);
        float w3 = __ldg(&g_WmF[3 * D + j]);
        for (int k = 0; k < D; k += 4) {
            float n0w = w0, n1w = w1, n2w = w2, n3w = w3;
            if (k + 4 < D) {
                w0 = __ldg(&g_WmF[(k + 4) * D + j]);
                w1 = __ldg(&g_WmF[(k + 5) * D + j]);
                w2 = __ldg(&g_WmF[(k + 6) * D + j]);
                w3 = __ldg(&g_WmF[(k + 7) * D + j]);
            }
            const float4* r0 = (const float4*)&aT[(k + 0) * TPAD];
            const float4* r1 = (const float4*)&aT[(k + 1) * TPAD];
            const float4* r2 = (const float4*)&aT[(k + 2) * TPAD];
            const float4* r3 = (const float4*)&aT[(k + 3) * TPAD];
            #pragma unroll
            for (int r4 = 0; r4 < TM / 4; r4++) {
                float4 a0 = r0[r4], a1 = r1[r4], a2 = r2[r4], a3 = r3[r4];
                acc[4*r4+0] += a0.x * n0w + a1.x * n1w + a2.x * n2w + a3.x * n3w;
                acc[4*r4+1] += a0.y * n0w + a1.y * n1w + a2.y * n2w + a3.y * n3w;
                acc[4*r4+2] += a0.z * n0w + a1.z * n1w + a2.z * n2w + a3.z * n3w;
                acc[4*r4+3] += a0.w * n0w + a1.w * n1w + a2.w * n2w + a3.w * n3w;
            }
        }
    }
    __syncthreads();
    float* hS = aT;
    #pragma unroll
    for (int r = 0; r < TM; r++) hS[r * D + j] = acc[r];
    __syncthreads();

    int wid = j >> 5, lane = j & 31;
    for (int r = wid; r < TM; r += 8) {
        float s1 = 0.f, s2 = 0.f;
        #pragma unroll
        for (int c = lane; c < D; c += 32) { float x = hS[r * D + c]; s1 += x; s2 += x * x; }
        #pragma unroll
        for (int o = 16; o; o >>= 1) {
            s1 += __shfl_xor_sync(0xFFFFFFFFu, s1, o);
            s2 += __shfl_xor_sync(0xFFFFFFFFu, s2, o);
        }
        if (lane == 0) {
            float mu = s1 * (1.f / D);
            float var = s2 * (1.f / D) - mu * mu;
            red[0][r] = mu;
            red[1][r] = rsqrtf(var + 1e-5f);
        }
    }
    __syncthreads();

    float ga = gamma[j], be = beta[j];
    for (int r = 0; r < nvld; r++) {
        float v = (acc[r] - red[0][r]) * red[1][r] * ga + be;
        v = fmaxf(v, 0.f);
        atomicAdd(&g_gsum[sb[r] * D + j], v);
    }
    if (j < nvld) atomicAdd(&g_gcnt[sb[j]], 1.f);
}

// ---------------- final: divide pooled sums ----------------
__global__ __launch_bounds__(D) void k_final(float* __restrict__ out, int G) {
    int g = blockIdx.x, j = threadIdx.x;
    out[g * D + j] = g_gsum[g * D + j] / fmaxf(g_gcnt[g], 1.f);
}

// ---------------- launch ----------------
extern "C" void kernel_launch(void* const* d_in, const int* in_sizes, int n_in,
                              void* d_out, int out_size) {
    const float* node_s = (const float*)d_in[0];
    const float* node_v = (const float*)d_in[1];
    const float* edge_s = (const float*)d_in[2];
    const int*   edge_index = (const int*)d_in[3];
    const int*   batch  = (const int*)d_in[4];
    const float* Ws  = (const float*)d_in[5];
    const float* bs  = (const float*)d_in[6];
    const float* Wv  = (const float*)d_in[7];
    const float* bv  = (const float*)d_in[8];
    const float* We  = (const float*)d_in[9];
    const float* be  = (const float*)d_in[10];
    const float* Wm1 = (const float*)d_in[11];
    const float* bm1 = (const float*)d_in[12];
    const float* Wm2 = (const float*)d_in[13];
    const float* bm2 = (const float*)d_in[14];
    const float* Wn  = (const float*)d_in[15];
    const float* bn  = (const float*)d_in[16];
    const float* gamma = (const float*)d_in[17];
    const float* beta  = (const float*)d_in[18];

    int N = in_sizes[0] / 23;
    int E = in_sizes[2] / 17;
    int G = out_size / D;

    k_zero<<<256, 256>>>(N, G);
    k_hist<<<(E + 255) / 256, 256>>>(edge_index, E);
    k_wef<<<18, D>>>(We, be, Wm1);
    k_fold2<<<24, D>>>(Ws, bs, Wm1, bm1);
    k_fold3<<<D + 24, D>>>(Wm2, bm2, Ws, bs, Wn, bn);
    k_scan<<<1, 1024>>>(N);
    k_scatter<<<(E + 255) / 256, 256>>>(edge_index, edge_s, E);
    k_nodeEmb<<<(N + TM - 1) / TM, D>>>(node_s, node_v, Wv, bv, Wm1, N);
    k_edgeCSR<<<(N + TM - 1) / TM, D>>>(N);
    k_node2<<<(N + TM - 1) / TM, D>>>(node_s, Wn, gamma, beta, batch, N);
    k_final<<<G, D>>>((float*)d_out, G);
}

// round 11
// speedup vs baseline: 1.5302x; 1.0919x over previous
#include <cuda_runtime.h>
#include <cuda_bf16.h>
#include <math.h>

#define D 256
#define VD 16
#define TM 32          // rows (nodes) per CTA
#define TPAD 36        // padded row length for transposed SMEM tiles (144B, 16B-aligned)
#define CH 128         // edges per shared chunk in edge kernel
#define PF 4           // Qs prefetch depth
#define MAXN 50000
#define MAXE 400000
#define MAXG 256

typedef unsigned long long ull;

// ---- packed f32x2 helpers (sm_103a) ----
__device__ __forceinline__ ull pk2(float lo, float hi) {
    ull r; asm("mov.b64 %0, {%1,%2};" : "=l"(r) : "f"(lo), "f"(hi)); return r;
}
__device__ __forceinline__ ull fma2(ull a, ull b, ull c) {
    ull d; asm("fma.rn.f32x2 %0, %1, %2, %3;" : "=l"(d) : "l"(a), "l"(b), "l"(c)); return d;
}
__device__ __forceinline__ ull add2(ull a, ull b) {
    ull d; asm("add.rn.f32x2 %0, %1, %2;" : "=l"(d) : "l"(a), "l"(b)); return d;
}
__device__ __forceinline__ float2 upk(ull v) {
    float2 f; asm("mov.b64 {%0,%1}, %2;" : "=f"(f.x), "=f"(f.y) : "l"(v)); return f;
}

// ---------------- scratch ----------------
__device__ float g_vn  [MAXN * VD];
__device__ float g_Pd  [MAXN * D];
__device__ float g_Qs  [MAXN * D];
__device__ float g_agg [MAXN * D];
__device__ float g_WeF [17 * D];
__device__ float g_beF [D];
__device__ float g_AP  [23 * D];
__device__ float g_AQ  [23 * D];
__device__ float g_bP  [D];
__device__ float g_bQ  [D];
__device__ float g_AH  [23 * D];
__device__ float g_WmF [D * D];
__device__ float g_bH  [D];
__device__ float g_gsum[MAXG * D];
__device__ float g_gcnt[MAXG];
// CSR sort scratch
__device__ int   g_rowcnt[MAXN];
__device__ int   g_roff  [MAXN + 1];
__device__ int   g_cursor[MAXN];
__device__ int   g_esrc  [MAXE];
__device__ int   g_erow  [MAXE];
__device__ float g_es    [MAXE * 20];

// ---------------- zero small accumulated buffers ----------------
__global__ void k_zero(int N, int G) {
    int i = blockIdx.x * blockDim.x + threadIdx.x;
    int gd = G * D;
    int total = gd + G + N;
    for (; i < total; i += gridDim.x * blockDim.x) {
        if (i < gd)           g_gsum[i] = 0.f;
        else if (i < gd + G)  g_gcnt[i - gd] = 0.f;
        else                  g_rowcnt[i - gd - G] = 0;
    }
}

// ---------------- histogram of dst ----------------
__global__ void k_hist(const int* __restrict__ edge_index, int E) {
    int i = blockIdx.x * blockDim.x + threadIdx.x;
    if (i < E) atomicAdd(&g_rowcnt[edge_index[E + i]], 1);
}

// ---------------- single-block exclusive scan over rowcnt ----------------
__global__ __launch_bounds__(1024) void k_scan(int N) {
    __shared__ int wsum[32];
    __shared__ int carry_s;
    int tid = threadIdx.x, lane = tid & 31, wid = tid >> 5;
    if (tid == 0) carry_s = 0;
    __syncthreads();
    for (int base = 0; base < N; base += 1024) {
        int idx = base + tid;
        int v = (idx < N) ? g_rowcnt[idx] : 0;
        int inc = v;
        #pragma unroll
        for (int o = 1; o < 32; o <<= 1) {
            int t = __shfl_up_sync(0xFFFFFFFFu, inc, o);
            if (lane >= o) inc += t;
        }
        if (lane == 31) wsum[wid] = inc;
        __syncthreads();
        if (wid == 0) {
            int s = wsum[lane];
            #pragma unroll
            for (int o = 1; o < 32; o <<= 1) {
                int t = __shfl_up_sync(0xFFFFFFFFu, s, o);
                if (lane >= o) s += t;
            }
            wsum[lane] = s;
        }
        __syncthreads();
        int carry = carry_s;
        int excl = carry + (wid ? wsum[wid - 1] : 0) + inc - v;
        if (idx < N) { g_roff[idx] = excl; g_cursor[idx] = excl; }
        __syncthreads();
        if (tid == 0) carry_s = carry + wsum[31];
        __syncthreads();
    }
    if (tid == 0) g_roff[N] = carry_s;
}

// ---------------- scatter edges into sorted (by dst) arrays ----------------
__global__ void k_scatter(const int* __restrict__ edge_index,
                          const float* __restrict__ edge_s, int E) {
    int e = blockIdx.x * blockDim.x + threadIdx.x;
    if (e >= E) return;
    int src = edge_index[e];
    int dst = edge_index[E + e];
    int pos = atomicAdd(&g_cursor[dst], 1);
    g_esrc[pos] = src;
    g_erow[pos] = dst;
    const float* es = edge_s + (long long)e * 17;
    float v[17];
    #pragma unroll
    for (int k = 0; k < 17; k++) v[k] = es[k];
    float4* dst4 = (float4*)&g_es[(long long)pos * 20];
    dst4[0] = make_float4(v[0], v[1], v[2], v[3]);
    dst4[1] = make_float4(v[4], v[5], v[6], v[7]);
    dst4[2] = make_float4(v[8], v[9], v[10], v[11]);
    dst4[3] = make_float4(v[12], v[13], v[14], v[15]);
    g_es[(long long)pos * 20 + 16] = v[16];
}

// ---------------- merged folds: wef (18) | fold2 (24) | fold3 (280) ----------------
__global__ __launch_bounds__(D) void k_folds(const float* __restrict__ We,
                                             const float* __restrict__ be,
                                             const float* __restrict__ Wm1,
                                             const float* __restrict__ Ws,
                                             const float* __restrict__ bs,
                                             const float* __restrict__ bm1,
                                             const float* __restrict__ Wm2,
                                             const float* __restrict__ bm2,
                                             const float* __restrict__ Wn,
                                             const float* __restrict__ bn) {
    __shared__ float row[D];
    int j = threadIdx.x, bb = blockIdx.x;
    if (bb < 18) {
        int b = bb;
        row[j] = (b < 17) ? We[b * D + j] : be[j];
        __syncthreads();
        float a0 = 0.f, a1 = 0.f, a2 = 0.f, a3 = 0.f;
        #pragma unroll 8
        for (int c = 0; c < D; c += 4) {
            a0 += row[c + 0] * Wm1[(528 + c + 0) * D + j];
            a1 += row[c + 1] * Wm1[(528 + c + 1) * D + j];
            a2 += row[c + 2] * Wm1[(528 + c + 2) * D + j];
            a3 += row[c + 3] * Wm1[(528 + c + 3) * D + j];
        }
        float a = (a0 + a1) + (a2 + a3);
        if (b < 17) g_WeF[b * D + j] = a;
        else        g_beF[j] = a;
    } else if (bb < 42) {
        int b = bb - 18;
        row[j] = (b < 23) ? Ws[b * D + j] : bs[j];
        __syncthreads();
        float p0 = 0.f, p1 = 0.f, q0 = 0.f, q1 = 0.f;
        #pragma unroll 8
        for (int c = 0; c < D; c += 2) {
            float r0 = row[c], r1 = row[c + 1];
            p0 += r0 * Wm1[(c + 0) * D + j];
            p1 += r1 * Wm1[(c + 1) * D + j];
            q0 += r0 * Wm1[(D + c + 0) * D + j];
            q1 += r1 * Wm1[(D + c + 1) * D + j];
        }
        float aP = p0 + p1, aQ = q0 + q1;
        if (b < 23) { g_AP[b * D + j] = aP; g_AQ[b * D + j] = aQ; }
        else        { g_bP[j] = aP + bm1[j]; g_bQ[j] = aQ; }
    } else {
        int b = bb - 42;
        if (b < D)            row[j] = Wm2[b * D + j];
        else if (b < D + 23)  row[j] = Ws[(b - D) * D + j];
        else                  row[j] = bs[j] + bm2[j];
        __syncthreads();
        float a0 = 0.f, a1 = 0.f, a2 = 0.f, a3 = 0.f;
        #pragma unroll 8
        for (int c = 0; c < D; c += 4) {
            a0 += row[c + 0] * Wn[(c + 0) * D + j];
            a1 += row[c + 1] * Wn[(c + 1) * D + j];
            a2 += row[c + 2] * Wn[(c + 2) * D + j];
            a3 += row[c + 3] * Wn[(c + 3) * D + j];
        }
        float a = (a0 + a1) + (a2 + a3);
        if (b < D)            g_WmF[b * D + j] = a;
        else if (b < D + 23)  g_AH[(b - D) * D + j] = a;
        else                  g_bH[j] = a + bn[j];
    }
}

// ---------------- node embed + first-layer precompute (f32x2) ----------------
__global__ __launch_bounds__(D) void k_nodeEmb(const float* __restrict__ node_s,
                                               const float* __restrict__ node_v,
                                               const float* __restrict__ Wv,
                                               const float* __restrict__ bv,
                                               const float* __restrict__ Wm1,
                                               int N) {
    __shared__ __align__(16) float nsT[23][TM];      // k-major: row-pairs contiguous
    __shared__ float nv[TM][12];
    __shared__ __align__(16) float vnT[VD][TM + 4];
    __shared__ float sWv[4 * VD];
    __shared__ float sbv[VD];
    int j = threadIdx.x;
    int n0 = blockIdx.x * TM;
    int nvld = min(TM, N - n0);

    for (int i = j; i < TM * 23; i += D) {
        int r = i / 23, k = i % 23;
        nsT[k][r] = (r < nvld) ? node_s[(n0 + r) * 23 + k] : 0.f;
    }
    for (int i = j; i < nvld * 12; i += D) nv[i / 12][i % 12] = node_v[n0 * 12 + i];
    if (j < 4 * VD) sWv[j] = Wv[j];
    if (j < VD) sbv[j] = bv[j];
    __syncthreads();

    for (int idx = j; idx < TM * VD; idx += D) {
        int r = idx / VD, o = idx % VD;
        float val = 0.f;
        if (r < nvld) {
            float x = sbv[o], y = sbv[o], z = sbv[o];
            #pragma unroll
            for (int k = 0; k < 4; k++) {
                float w = sWv[k * VD + o];
                x += nv[r][k * 3 + 0] * w;
                y += nv[r][k * 3 + 1] * w;
                z += nv[r][k * 3 + 2] * w;
            }
            val = sqrtf(x * x + y * y + z * z);
            g_vn[(n0 + r) * VD + o] = val;
        }
        vnT[o][r] = val;
    }
    __syncthreads();

    ull accP2[TM / 2], accQ2[TM / 2];
    {
        ull bp2 = pk2(g_bP[j], g_bP[j]);
        ull bq2 = pk2(g_bQ[j], g_bQ[j]);
        #pragma unroll
        for (int r = 0; r < TM / 2; r++) { accP2[r] = bp2; accQ2[r] = bq2; }
    }

    #pragma unroll 4
    for (int k = 0; k < 23; k++) {
        float wP = __ldg(&g_AP[k * D + j]);
        float wQ = __ldg(&g_AQ[k * D + j]);
        ull wP2 = pk2(wP, wP), wQ2 = pk2(wQ, wQ);
        const ull* rowp = (const ull*)&nsT[k][0];
        #pragma unroll
        for (int r = 0; r < TM / 2; r++) {
            ull a = rowp[r];
            accP2[r] = fma2(a, wP2, accP2[r]);
            accQ2[r] = fma2(a, wQ2, accQ2[r]);
        }
    }
    const float* W1V = Wm1 + 512 * D;
    #pragma unroll 4
    for (int k = 0; k < VD; k++) {
        float wV = __ldg(&W1V[k * D + j]);
        ull wV2 = pk2(wV, wV);
        const ull* rowp = (const ull*)&vnT[k][0];
        #pragma unroll
        for (int r = 0; r < TM / 2; r++) accQ2[r] = fma2(rowp[r], wV2, accQ2[r]);
    }
    for (int r2 = 0; r2 < TM / 2; r2++) {
        float2 p = upk(accP2[r2]), q = upk(accQ2[r2]);
        int r = 2 * r2;
        if (r < nvld)     { g_Pd[(n0 + r) * D + j] = p.x;     g_Qs[(n0 + r) * D + j] = q.x; }
        if (r + 1 < nvld) { g_Pd[(n0 + r + 1) * D + j] = p.y; g_Qs[(n0 + r + 1) * D + j] = q.y; }
    }
}

// ---------------- edge kernel (CSR, f32x2 dot, PF-deep Qs prefetch) ----------------
__global__ __launch_bounds__(D) void k_edgeCSR(int N) {
    __shared__ float sPd[TM * D];
    __shared__ __align__(16) float sEs[CH][20];
    __shared__ int   sSrc[CH];
    __shared__ int   sRow[CH];
    int j = threadIdx.x;
    int n0 = blockIdx.x * TM;
    int nvld = min(TM, N - n0);

    for (int i = j; i < nvld * D; i += D) {
        int r = i >> 8, k = i & 255;
        sPd[r * D + k] = g_Pd[(n0 + r) * D + k];
    }
    int e0 = g_roff[n0];
    int e1 = g_roff[n0 + nvld];

    ull w2[8];
    float wf16;
    {
        float wf[17];
        #pragma unroll
        for (int k = 0; k < 17; k++) wf[k] = g_WeF[k * D + j];
        #pragma unroll
        for (int k = 0; k < 8; k++) w2[k] = pk2(wf[2 * k], wf[2 * k + 1]);
        wf16 = wf[16];
    }
    float bef = g_beF[j];

    int cur = -1;
    float a = 0.f, bpd = 0.f;

    for (int base = e0; base < e1; base += CH) {
        int cnt = min(CH, e1 - base);
        __syncthreads();
        for (int t = j; t < cnt * 20; t += D)
            sEs[t / 20][t % 20] = g_es[(long long)base * 20 + t];
        for (int t = j; t < cnt; t += D) {
            sSrc[t] = g_esrc[base + t];
            sRow[t] = g_erow[base + t] - n0;
        }
        __syncthreads();

        float q[PF];
        #pragma unroll
        for (int p = 0; p < PF; p++)
            q[p] = (p < cnt) ? __ldg(&g_Qs[sSrc[p] * D + j]) : 0.f;

        for (int i = 0; i < cnt; i += PF) {
            #pragma unroll
            for (int u = 0; u < PF; u++) {
                int idx = i + u;
                if (idx >= cnt) break;
                float qc = q[u];
                int nidx = idx + PF;
                q[u] = (nidx < cnt) ? __ldg(&g_Qs[sSrc[nidx] * D + j]) : 0.f;
                int r = sRow[idx];
                if (r != cur) {
                    if (cur >= 0) g_agg[(n0 + cur) * D + j] = a;
                    cur = r; a = 0.f;
                    bpd = bef + sPd[r * D + j];
                }
                const ulonglong2* ep = (const ulonglong2*)sEs[idx];
                ulonglong2 p0 = ep[0], p1 = ep[1];
                ull ha = pk2(bpd + qc, sEs[idx][16] * wf16);
                ull hb = pk2(0.f, 0.f);
                ha = fma2(p0.x, w2[0], ha);
                hb = fma2(p0.y, w2[1], hb);
                ha = fma2(p1.x, w2[2], ha);
                hb = fma2(p1.y, w2[3], hb);
                ulonglong2 p2 = ep[2], p3 = ep[3];
                ha = fma2(p2.x, w2[4], ha);
                hb = fma2(p2.y, w2[5], hb);
                ha = fma2(p3.x, w2[6], ha);
                hb = fma2(p3.y, w2[7], hb);
                float2 hf = upk(add2(ha, hb));
                a += fmaxf(hf.x + hf.y, 0.f);
            }
        }
    }
    if (cur >= 0) g_agg[(n0 + cur) * D + j] = a;
}

// ---------------- node output: folded GEMMs (f32x2) + LN + ReLU + pooling ----------------
__global__ __launch_bounds__(D) void k_node2(const float* __restrict__ node_s,
                                             const float* __restrict__ Wn,
                                             const float* __restrict__ gamma,
                                             const float* __restrict__ beta,
                                             const int* __restrict__ batch,
                                             int N) {
    __shared__ __align__(16) float aT[D * TPAD];
    __shared__ __align__(16) float ns2T[23][TM];
    __shared__ __align__(16) float vnT[VD][TPAD];
    __shared__ float rc[TM];
    __shared__ float red[2][TM];
    __shared__ int sb[TM];
    int j = threadIdx.x;
    int n0 = blockIdx.x * TM;
    int nvld = min(TM, N - n0);

    if (j < TM) {
        float deg = 0.f;
        if (j < nvld) {
            int n = n0 + j;
            deg = (float)(g_roff[n + 1] - g_roff[n]);
            sb[j] = batch[n];
        } else sb[j] = 0;
        rc[j] = 1.f / fmaxf(deg, 1.f);
    }
    for (int i = j; i < TM * 23; i += D) {
        int r = i / 23, k = i % 23;
        ns2T[k][r] = (r < nvld) ? node_s[(n0 + r) * 23 + k] : 0.f;
    }
    for (int i = j; i < TM * VD; i += D) {
        int r = i / VD, k = i % VD;
        vnT[k][r] = (r < nvld) ? g_vn[(n0 + r) * VD + k] : 0.f;
    }
    __syncthreads();
    for (int i = j; i < TM * D; i += D) {
        int r = i >> 8, k = i & 255;
        aT[k * TPAD + r] = (r < nvld) ? g_agg[(n0 + r) * D + k] * rc[r] : 0.f;
    }
    __syncthreads();

    ull acc2[TM / 2];
    {
        float bh = g_bH[j];
        ull b2 = pk2(bh, bh);
        #pragma unroll
        for (int r = 0; r < TM / 2; r++) acc2[r] = b2;
    }

    #pragma unroll 4
    for (int k = 0; k < 23; k++) {
        float w = __ldg(&g_AH[k * D + j]);
        ull w2 = pk2(w, w);
        const ull* rowp = (const ull*)&ns2T[k][0];
        #pragma unroll
        for (int r = 0; r < TM / 2; r++) acc2[r] = fma2(rowp[r], w2, acc2[r]);
    }
    const float* WnV = Wn + D * D;
    #pragma unroll 4
    for (int k = 0; k < VD; k++) {
        float w = __ldg(&WnV[k * D + j]);
        ull w2 = pk2(w, w);
        const ull* rowp = (const ull*)&vnT[k][0];
        #pragma unroll
        for (int r = 0; r < TM / 2; r++) acc2[r] = fma2(rowp[r], w2, acc2[r]);
    }
    // main 256-K GEMM over g_WmF, weight prefetch + packed FMA
    {
        float w0 = __ldg(&g_WmF[0 * D + j]);
        float w1 = __ldg(&g_WmF[1 * D + j]);
        float w2s = __ldg(&g_WmF[2 * D + j]);
        float w3 = __ldg(&g_WmF[3 * D + j]);
        for (int k = 0; k < D; k += 4) {
            float c0 = w0, c1 = w1, c2 = w2s, c3 = w3;
            if (k + 4 < D) {
                w0 = __ldg(&g_WmF[(k + 4) * D + j]);
                w1 = __ldg(&g_WmF[(k + 5) * D + j]);
                w2s = __ldg(&g_WmF[(k + 6) * D + j]);
                w3 = __ldg(&g_WmF[(k + 7) * D + j]);
            }
            ull d0 = pk2(c0, c0), d1 = pk2(c1, c1), d2 = pk2(c2, c2), d3 = pk2(c3, c3);
            const ull* r0 = (const ull*)&aT[(k + 0) * TPAD];
            const ull* r1 = (const ull*)&aT[(k + 1) * TPAD];
            const ull* r2 = (const ull*)&aT[(k + 2) * TPAD];
            const ull* r3 = (const ull*)&aT[(k + 3) * TPAD];
            #pragma unroll
            for (int p = 0; p < TM / 2; p++) {
                acc2[p] = fma2(r0[p], d0, acc2[p]);
                acc2[p] = fma2(r1[p], d1, acc2[p]);
                acc2[p] = fma2(r2[p], d2, acc2[p]);
                acc2[p] = fma2(r3[p], d3, acc2[p]);
            }
        }
    }
    float acc[TM];
    #pragma unroll
    for (int r2 = 0; r2 < TM / 2; r2++) {
        float2 f = upk(acc2[r2]);
        acc[2 * r2] = f.x;
        acc[2 * r2 + 1] = f.y;
    }
    __syncthreads();
    float* hS = aT;
    #pragma unroll
    for (int r = 0; r < TM; r++) hS[r * D + j] = acc[r];
    __syncthreads();

    int wid = j >> 5, lane = j & 31;
    for (int r = wid; r < TM; r += 8) {
        float s1 = 0.f, s2 = 0.f;
        #pragma unroll
        for (int c = lane; c < D; c += 32) { float x = hS[r * D + c]; s1 += x; s2 += x * x; }
        #pragma unroll
        for (int o = 16; o; o >>= 1) {
            s1 += __shfl_xor_sync(0xFFFFFFFFu, s1, o);
            s2 += __shfl_xor_sync(0xFFFFFFFFu, s2, o);
        }
        if (lane == 0) {
            float mu = s1 * (1.f / D);
            float var = s2 * (1.f / D) - mu * mu;
            red[0][r] = mu;
            red[1][r] = rsqrtf(var + 1e-5f);
        }
    }
    __syncthreads();

    float ga = gamma[j], be = beta[j];
    for (int r = 0; r < nvld; r++) {
        float v = (acc[r] - red[0][r]) * red[1][r] * ga + be;
        v = fmaxf(v, 0.f);
        atomicAdd(&g_gsum[sb[r] * D + j], v);
    }
    if (j < nvld) atomicAdd(&g_gcnt[sb[j]], 1.f);
}

// ---------------- final: divide pooled sums ----------------
__global__ __launch_bounds__(D) void k_final(float* __restrict__ out, int G) {
    int g = blockIdx.x, j = threadIdx.x;
    out[g * D + j] = g_gsum[g * D + j] / fmaxf(g_gcnt[g], 1.f);
}

// ---------------- launch ----------------
extern "C" void kernel_launch(void* const* d_in, const int* in_sizes, int n_in,
                              void* d_out, int out_size) {
    const float* node_s = (const float*)d_in[0];
    const float* node_v = (const float*)d_in[1];
    const float* edge_s = (const float*)d_in[2];
    const int*   edge_index = (const int*)d_in[3];
    const int*   batch  = (const int*)d_in[4];
    const float* Ws  = (const float*)d_in[5];
    const float* bs  = (const float*)d_in[6];
    const float* Wv  = (const float*)d_in[7];
    const float* bv  = (const float*)d_in[8];
    const float* We  = (const float*)d_in[9];
    const float* be  = (const float*)d_in[10];
    const float* Wm1 = (const float*)d_in[11];
    const float* bm1 = (const float*)d_in[12];
    const float* Wm2 = (const float*)d_in[13];
    const float* bm2 = (const float*)d_in[14];
    const float* Wn  = (const float*)d_in[15];
    const float* bn  = (const float*)d_in[16];
    const float* gamma = (const float*)d_in[17];
    const float* beta  = (const float*)d_in[18];

    int N = in_sizes[0] / 23;
    int E = in_sizes[2] / 17;
    int G = out_size / D;

    k_zero<<<256, 256>>>(N, G);
    k_hist<<<(E + 255) / 256, 256>>>(edge_index, E);
    k_folds<<<42 + D + 24, D>>>(We, be, Wm1, Ws, bs, bm1, Wm2, bm2, Wn, bn);
    k_scan<<<1, 1024>>>(N);
    k_scatter<<<(E + 255) / 256, 256>>>(edge_index, edge_s, E);
    k_nodeEmb<<<(N + TM - 1) / TM, D>>>(node_s, node_v, Wv, bv, Wm1, N);
    k_edgeCSR<<<(N + TM - 1) / TM, D>>>(N);
    k_node2<<<(N + TM - 1) / TM, D>>>(node_s, Wn, gamma, beta, batch, N);
    k_final<<<G, D>>>((float*)d_out, G);
}

// round 12
// speedup vs baseline: 1.6124x; 1.0537x over previous
#include <cuda_runtime.h>
#include <cuda_bf16.h>
#include <math.h>

#define D 256
#define VD 16
#define TM 32          // rows (nodes) per CTA
#define TPAD 36        // padded row length for transposed SMEM tiles (144B, 16B-aligned)
#define CH 128         // edges per shared chunk in edge kernel
#define PF 4           // Qs prefetch depth
#define MAXN 50000
#define MAXE 400000
#define MAXG 256
#define SCB 1024       // scan block size
#define MAXSB ((MAXN + SCB - 1) / SCB)

typedef unsigned long long ull;

// ---- packed f32x2 helpers (sm_103a) ----
__device__ __forceinline__ ull pk2(float lo, float hi) {
    ull r; asm("mov.b64 %0, {%1,%2};" : "=l"(r) : "f"(lo), "f"(hi)); return r;
}
__device__ __forceinline__ ull fma2(ull a, ull b, ull c) {
    ull d; asm("fma.rn.f32x2 %0, %1, %2, %3;" : "=l"(d) : "l"(a), "l"(b), "l"(c)); return d;
}
__device__ __forceinline__ ull add2(ull a, ull b) {
    ull d; asm("add.rn.f32x2 %0, %1, %2;" : "=l"(d) : "l"(a), "l"(b)); return d;
}
__device__ __forceinline__ float2 upk(ull v) {
    float2 f; asm("mov.b64 {%0,%1}, %2;" : "=f"(f.x), "=f"(f.y) : "l"(v)); return f;
}

// ---------------- scratch ----------------
__device__ float g_vn  [MAXN * VD];
__device__ float g_Pd  [MAXN * D];
__device__ float g_Qs  [MAXN * D];
__device__ float g_agg [MAXN * D];
__device__ float g_WeF [17 * D];
__device__ float g_beF [D];
__device__ float g_AP  [23 * D];
__device__ float g_AQ  [23 * D];
__device__ float g_bP  [D];
__device__ float g_bQ  [D];
__device__ float g_AH  [23 * D];
__device__ float g_WmF [D * D];
__device__ float g_bH  [D];
__device__ float g_gsum[MAXG * D];
__device__ float g_gcnt[MAXG];
// CSR sort scratch
__device__ int   g_rowcnt[MAXN];
__device__ int   g_roff  [MAXN + 1];
__device__ int   g_cursor[MAXN];
__device__ int   g_bsum  [MAXSB];
__device__ int   g_boff  [MAXSB];
__device__ int   g_esrc  [MAXE];
__device__ int   g_erow  [MAXE];
__device__ float g_es    [MAXE * 20];

// ---------------- zero small accumulated buffers ----------------
__global__ void k_zero(int N, int G) {
    int i = blockIdx.x * blockDim.x + threadIdx.x;
    int gd = G * D;
    int total = gd + G + N;
    for (; i < total; i += gridDim.x * blockDim.x) {
        if (i < gd)           g_gsum[i] = 0.f;
        else if (i < gd + G)  g_gcnt[i - gd] = 0.f;
        else                  g_rowcnt[i - gd - G] = 0;
    }
}

// ---------------- histogram of dst ----------------
__global__ void k_hist(const int* __restrict__ edge_index, int E) {
    int i = blockIdx.x * blockDim.x + threadIdx.x;
    if (i < E) atomicAdd(&g_rowcnt[edge_index[E + i]], 1);
}

// ---------------- multi-block scan, phase A: per-block local exclusive scan ----------------
__global__ __launch_bounds__(SCB) void k_scanA(int N) {
    __shared__ int wsum[32];
    int tid = threadIdx.x, lane = tid & 31, wid = tid >> 5;
    int idx = blockIdx.x * SCB + tid;
    int v = (idx < N) ? g_rowcnt[idx] : 0;
    int inc = v;
    #pragma unroll
    for (int o = 1; o < 32; o <<= 1) {
        int t = __shfl_up_sync(0xFFFFFFFFu, inc, o);
        if (lane >= o) inc += t;
    }
    if (lane == 31) wsum[wid] = inc;
    __syncthreads();
    if (wid == 0) {
        int s = wsum[lane];
        #pragma unroll
        for (int o = 1; o < 32; o <<= 1) {
            int t = __shfl_up_sync(0xFFFFFFFFu, s, o);
            if (lane >= o) s += t;
        }
        wsum[lane] = s;
    }
    __syncthreads();
    int excl = (wid ? wsum[wid - 1] : 0) + inc - v;   // local exclusive
    if (idx < N) g_roff[idx] = excl;
    if (tid == SCB - 1) g_bsum[blockIdx.x] = excl + v;
}

// ---------------- phase B: scan the (<=MAXSB) block sums in one small block ----------------
__global__ __launch_bounds__(64) void k_scanB(int nb, int N) {
    __shared__ int sh[MAXSB];
    int tid = threadIdx.x;
    for (int i = tid; i < nb; i += 64) sh[i] = g_bsum[i];
    __syncthreads();
    if (tid == 0) {
        int run = 0;
        for (int i = 0; i < nb; i++) { int t = sh[i]; sh[i] = run; run += t; }
        g_roff[N] = run;
    }
    __syncthreads();
    for (int i = tid; i < nb; i += 64) g_boff[i] = sh[i];
}

// ---------------- phase C: add block offsets, fill cursor ----------------
__global__ __launch_bounds__(SCB) void k_scanC(int N) {
    int idx = blockIdx.x * SCB + threadIdx.x;
    if (idx < N) {
        int v = g_roff[idx] + g_boff[blockIdx.x];
        g_roff[idx] = v;
        g_cursor[idx] = v;
    }
}

// ---------------- scatter edges into sorted (by dst) arrays ----------------
__global__ void k_scatter(const int* __restrict__ edge_index,
                          const float* __restrict__ edge_s, int E) {
    int e = blockIdx.x * blockDim.x + threadIdx.x;
    if (e >= E) return;
    int src = edge_index[e];
    int dst = edge_index[E + e];
    int pos = atomicAdd(&g_cursor[dst], 1);
    g_esrc[pos] = src;
    g_erow[pos] = dst;
    const float* es = edge_s + (long long)e * 17;
    float v[17];
    #pragma unroll
    for (int k = 0; k < 17; k++) v[k] = es[k];
    float4* dst4 = (float4*)&g_es[(long long)pos * 20];
    dst4[0] = make_float4(v[0], v[1], v[2], v[3]);
    dst4[1] = make_float4(v[4], v[5], v[6], v[7]);
    dst4[2] = make_float4(v[8], v[9], v[10], v[11]);
    dst4[3] = make_float4(v[12], v[13], v[14], v[15]);
    g_es[(long long)pos * 20 + 16] = v[16];
}

// ---------------- merged folds: wef (18) | fold2 (24) | fold3 (280) ----------------
__global__ __launch_bounds__(D) void k_folds(const float* __restrict__ We,
                                             const float* __restrict__ be,
                                             const float* __restrict__ Wm1,
                                             const float* __restrict__ Ws,
                                             const float* __restrict__ bs,
                                             const float* __restrict__ bm1,
                                             const float* __restrict__ Wm2,
                                             const float* __restrict__ bm2,
                                             const float* __restrict__ Wn,
                                             const float* __restrict__ bn) {
    __shared__ float row[D];
    int j = threadIdx.x, bb = blockIdx.x;
    if (bb < 18) {
        int b = bb;
        row[j] = (b < 17) ? We[b * D + j] : be[j];
        __syncthreads();
        float a0 = 0.f, a1 = 0.f, a2 = 0.f, a3 = 0.f;
        #pragma unroll 8
        for (int c = 0; c < D; c += 4) {
            a0 += row[c + 0] * Wm1[(528 + c + 0) * D + j];
            a1 += row[c + 1] * Wm1[(528 + c + 1) * D + j];
            a2 += row[c + 2] * Wm1[(528 + c + 2) * D + j];
            a3 += row[c + 3] * Wm1[(528 + c + 3) * D + j];
        }
        float a = (a0 + a1) + (a2 + a3);
        if (b < 17) g_WeF[b * D + j] = a;
        else        g_beF[j] = a;
    } else if (bb < 42) {
        int b = bb - 18;
        row[j] = (b < 23) ? Ws[b * D + j] : bs[j];
        __syncthreads();
        float p0 = 0.f, p1 = 0.f, q0 = 0.f, q1 = 0.f;
        #pragma unroll 8
        for (int c = 0; c < D; c += 2) {
            float r0 = row[c], r1 = row[c + 1];
            p0 += r0 * Wm1[(c + 0) * D + j];
            p1 += r1 * Wm1[(c + 1) * D + j];
            q0 += r0 * Wm1[(D + c + 0) * D + j];
            q1 += r1 * Wm1[(D + c + 1) * D + j];
        }
        float aP = p0 + p1, aQ = q0 + q1;
        if (b < 23) { g_AP[b * D + j] = aP; g_AQ[b * D + j] = aQ; }
        else        { g_bP[j] = aP + bm1[j]; g_bQ[j] = aQ; }
    } else {
        int b = bb - 42;
        if (b < D)            row[j] = Wm2[b * D + j];
        else if (b < D + 23)  row[j] = Ws[(b - D) * D + j];
        else                  row[j] = bs[j] + bm2[j];
        __syncthreads();
        float a0 = 0.f, a1 = 0.f, a2 = 0.f, a3 = 0.f;
        #pragma unroll 8
        for (int c = 0; c < D; c += 4) {
            a0 += row[c + 0] * Wn[(c + 0) * D + j];
            a1 += row[c + 1] * Wn[(c + 1) * D + j];
            a2 += row[c + 2] * Wn[(c + 2) * D + j];
            a3 += row[c + 3] * Wn[(c + 3) * D + j];
        }
        float a = (a0 + a1) + (a2 + a3);
        if (b < D)            g_WmF[b * D + j] = a;
        else if (b < D + 23)  g_AH[(b - D) * D + j] = a;
        else                  g_bH[j] = a + bn[j];
    }
}

// ---------------- node embed + first-layer precompute (f32x2) ----------------
__global__ __launch_bounds__(D) void k_nodeEmb(const float* __restrict__ node_s,
                                               const float* __restrict__ node_v,
                                               const float* __restrict__ Wv,
                                               const float* __restrict__ bv,
                                               const float* __restrict__ Wm1,
                                               int N) {
    __shared__ __align__(16) float nsT[23][TM];
    __shared__ float nv[TM][12];
    __shared__ __align__(16) float vnT[VD][TM + 4];
    __shared__ float sWv[4 * VD];
    __shared__ float sbv[VD];
    int j = threadIdx.x;
    int n0 = blockIdx.x * TM;
    int nvld = min(TM, N - n0);

    for (int i = j; i < TM * 23; i += D) {
        int r = i / 23, k = i % 23;
        nsT[k][r] = (r < nvld) ? node_s[(n0 + r) * 23 + k] : 0.f;
    }
    for (int i = j; i < nvld * 12; i += D) nv[i / 12][i % 12] = node_v[n0 * 12 + i];
    if (j < 4 * VD) sWv[j] = Wv[j];
    if (j < VD) sbv[j] = bv[j];
    __syncthreads();

    for (int idx = j; idx < TM * VD; idx += D) {
        int r = idx / VD, o = idx % VD;
        float val = 0.f;
        if (r < nvld) {
            float x = sbv[o], y = sbv[o], z = sbv[o];
            #pragma unroll
            for (int k = 0; k < 4; k++) {
                float w = sWv[k * VD + o];
                x += nv[r][k * 3 + 0] * w;
                y += nv[r][k * 3 + 1] * w;
                z += nv[r][k * 3 + 2] * w;
            }
            val = sqrtf(x * x + y * y + z * z);
            g_vn[(n0 + r) * VD + o] = val;
        }
        vnT[o][r] = val;
    }
    __syncthreads();

    ull accP2[TM / 2], accQ2[TM / 2];
    {
        ull bp2 = pk2(g_bP[j], g_bP[j]);
        ull bq2 = pk2(g_bQ[j], g_bQ[j]);
        #pragma unroll
        for (int r = 0; r < TM / 2; r++) { accP2[r] = bp2; accQ2[r] = bq2; }
    }

    #pragma unroll 4
    for (int k = 0; k < 23; k++) {
        float wP = __ldg(&g_AP[k * D + j]);
        float wQ = __ldg(&g_AQ[k * D + j]);
        ull wP2 = pk2(wP, wP), wQ2 = pk2(wQ, wQ);
        const ull* rowp = (const ull*)&nsT[k][0];
        #pragma unroll
        for (int r = 0; r < TM / 2; r++) {
            ull a = rowp[r];
            accP2[r] = fma2(a, wP2, accP2[r]);
            accQ2[r] = fma2(a, wQ2, accQ2[r]);
        }
    }
    const float* W1V = Wm1 + 512 * D;
    #pragma unroll 4
    for (int k = 0; k < VD; k++) {
        float wV = __ldg(&W1V[k * D + j]);
        ull wV2 = pk2(wV, wV);
        const ull* rowp = (const ull*)&vnT[k][0];
        #pragma unroll
        for (int r = 0; r < TM / 2; r++) accQ2[r] = fma2(rowp[r], wV2, accQ2[r]);
    }
    for (int r2 = 0; r2 < TM / 2; r2++) {
        float2 p = upk(accP2[r2]), q = upk(accQ2[r2]);
        int r = 2 * r2;
        if (r < nvld)     { g_Pd[(n0 + r) * D + j] = p.x;     g_Qs[(n0 + r) * D + j] = q.x; }
        if (r + 1 < nvld) { g_Pd[(n0 + r + 1) * D + j] = p.y; g_Qs[(n0 + r + 1) * D + j] = q.y; }
    }
}

// ---------------- edge kernel (CSR, f32x2 dot, PF-deep Qs prefetch) ----------------
__global__ __launch_bounds__(D) void k_edgeCSR(int N) {
    __shared__ float sPd[TM * D];
    __shared__ __align__(16) float sEs[CH][20];
    __shared__ int   sSrc[CH];
    __shared__ int   sRow[CH];
    int j = threadIdx.x;
    int n0 = blockIdx.x * TM;
    int nvld = min(TM, N - n0);

    for (int i = j; i < nvld * D; i += D) {
        int r = i >> 8, k = i & 255;
        sPd[r * D + k] = g_Pd[(n0 + r) * D + k];
    }
    int e0 = g_roff[n0];
    int e1 = g_roff[n0 + nvld];

    ull w2[8];
    float wf16;
    {
        float wf[17];
        #pragma unroll
        for (int k = 0; k < 17; k++) wf[k] = g_WeF[k * D + j];
        #pragma unroll
        for (int k = 0; k < 8; k++) w2[k] = pk2(wf[2 * k], wf[2 * k + 1]);
        wf16 = wf[16];
    }
    float bef = g_beF[j];

    int cur = -1;
    float a = 0.f, bpd = 0.f;

    for (int base = e0; base < e1; base += CH) {
        int cnt = min(CH, e1 - base);
        __syncthreads();
        for (int t = j; t < cnt * 20; t += D)
            sEs[t / 20][t % 20] = g_es[(long long)base * 20 + t];
        for (int t = j; t < cnt; t += D) {
            sSrc[t] = g_esrc[base + t];
            sRow[t] = g_erow[base + t] - n0;
        }
        __syncthreads();

        float q[PF];
        #pragma unroll
        for (int p = 0; p < PF; p++)
            q[p] = (p < cnt) ? __ldg(&g_Qs[sSrc[p] * D + j]) : 0.f;

        for (int i = 0; i < cnt; i += PF) {
            #pragma unroll
            for (int u = 0; u < PF; u++) {
                int idx = i + u;
                if (idx >= cnt) break;
                float qc = q[u];
                int nidx = idx + PF;
                q[u] = (nidx < cnt) ? __ldg(&g_Qs[sSrc[nidx] * D + j]) : 0.f;
                int r = sRow[idx];
                if (r != cur) {
                    if (cur >= 0) g_agg[(n0 + cur) * D + j] = a;
                    cur = r; a = 0.f;
                    bpd = bef + sPd[r * D + j];
                }
                const ulonglong2* ep = (const ulonglong2*)sEs[idx];
                ulonglong2 p0 = ep[0], p1 = ep[1];
                ull ha = pk2(bpd + qc, sEs[idx][16] * wf16);
                ull hb = pk2(0.f, 0.f);
                ha = fma2(p0.x, w2[0], ha);
                hb = fma2(p0.y, w2[1], hb);
                ha = fma2(p1.x, w2[2], ha);
                hb = fma2(p1.y, w2[3], hb);
                ulonglong2 p2 = ep[2], p3 = ep[3];
                ha = fma2(p2.x, w2[4], ha);
                hb = fma2(p2.y, w2[5], hb);
                ha = fma2(p3.x, w2[6], ha);
                hb = fma2(p3.y, w2[7], hb);
                float2 hf = upk(add2(ha, hb));
                a += fmaxf(hf.x + hf.y, 0.f);
            }
        }
    }
    if (cur >= 0) g_agg[(n0 + cur) * D + j] = a;
}

// ---------------- node output: folded GEMMs (f32x2) + LN + ReLU + pooling ----------------
__global__ __launch_bounds__(D) void k_node2(const float* __restrict__ node_s,
                                             const float* __restrict__ Wn,
                                             const float* __restrict__ gamma,
                                             const float* __restrict__ beta,
                                             const int* __restrict__ batch,
                                             int N) {
    __shared__ __align__(16) float aT[D * TPAD];
    __shared__ __align__(16) float ns2T[23][TM];
    __shared__ __align__(16) float vnT[VD][TPAD];
    __shared__ float rc[TM];
    __shared__ float red[2][TM];
    __shared__ int sb[TM];
    int j = threadIdx.x;
    int n0 = blockIdx.x * TM;
    int nvld = min(TM, N - n0);

    if (j < TM) {
        float deg = 0.f;
        if (j < nvld) {
            int n = n0 + j;
            deg = (float)(g_roff[n + 1] - g_roff[n]);
            sb[j] = batch[n];
        } else sb[j] = 0;
        rc[j] = 1.f / fmaxf(deg, 1.f);
    }
    for (int i = j; i < TM * 23; i += D) {
        int r = i / 23, k = i % 23;
        ns2T[k][r] = (r < nvld) ? node_s[(n0 + r) * 23 + k] : 0.f;
    }
    for (int i = j; i < TM * VD; i += D) {
        int r = i / VD, k = i % VD;
        vnT[k][r] = (r < nvld) ? g_vn[(n0 + r) * VD + k] : 0.f;
    }
    __syncthreads();
    for (int i = j; i < TM * D; i += D) {
        int r = i >> 8, k = i & 255;
        aT[k * TPAD + r] = (r < nvld) ? g_agg[(n0 + r) * D + k] * rc[r] : 0.f;
    }
    __syncthreads();

    ull acc2[TM / 2];
    {
        float bh = g_bH[j];
        ull b2 = pk2(bh, bh);
        #pragma unroll
        for (int r = 0; r < TM / 2; r++) acc2[r] = b2;
    }

    #pragma unroll 4
    for (int k = 0; k < 23; k++) {
        float w = __ldg(&g_AH[k * D + j]);
        ull w2 = pk2(w, w);
        const ull* rowp = (const ull*)&ns2T[k][0];
        #pragma unroll
        for (int r = 0; r < TM / 2; r++) acc2[r] = fma2(rowp[r], w2, acc2[r]);
    }
    const float* WnV = Wn + D * D;
    #pragma unroll 4
    for (int k = 0; k < VD; k++) {
        float w = __ldg(&WnV[k * D + j]);
        ull w2 = pk2(w, w);
        const ull* rowp = (const ull*)&vnT[k][0];
        #pragma unroll
        for (int r = 0; r < TM / 2; r++) acc2[r] = fma2(rowp[r], w2, acc2[r]);
    }
    {
        float w0 = __ldg(&g_WmF[0 * D + j]);
        float w1 = __ldg(&g_WmF[1 * D + j]);
        float w2s = __ldg(&g_WmF[2 * D + j]);
        float w3 = __ldg(&g_WmF[3 * D + j]);
        for (int k = 0; k < D; k += 4) {
            float c0 = w0, c1 = w1, c2 = w2s, c3 = w3;
            if (k + 4 < D) {
                w0 = __ldg(&g_WmF[(k + 4) * D + j]);
                w1 = __ldg(&g_WmF[(k + 5) * D + j]);
                w2s = __ldg(&g_WmF[(k + 6) * D + j]);
                w3 = __ldg(&g_WmF[(k + 7) * D + j]);
            }
            ull d0 = pk2(c0, c0), d1 = pk2(c1, c1), d2 = pk2(c2, c2), d3 = pk2(c3, c3);
            const ull* r0 = (const ull*)&aT[(k + 0) * TPAD];
            const ull* r1 = (const ull*)&aT[(k + 1) * TPAD];
            const ull* r2 = (const ull*)&aT[(k + 2) * TPAD];
            const ull* r3 = (const ull*)&aT[(k + 3) * TPAD];
            #pragma unroll
            for (int p = 0; p < TM / 2; p++) {
                acc2[p] = fma2(r0[p], d0, acc2[p]);
                acc2[p] = fma2(r1[p], d1, acc2[p]);
                acc2[p] = fma2(r2[p], d2, acc2[p]);
                acc2[p] = fma2(r3[p], d3, acc2[p]);
            }
        }
    }
    float acc[TM];
    #pragma unroll
    for (int r2 = 0; r2 < TM / 2; r2++) {
        float2 f = upk(acc2[r2]);
        acc[2 * r2] = f.x;
        acc[2 * r2 + 1] = f.y;
    }
    __syncthreads();
    float* hS = aT;
    #pragma unroll
    for (int r = 0; r < TM; r++) hS[r * D + j] = acc[r];
    __syncthreads();

    int wid = j >> 5, lane = j & 31;
    for (int r = wid; r < TM; r += 8) {
        float s1 = 0.f, s2 = 0.f;
        #pragma unroll
        for (int c = lane; c < D; c += 32) { float x = hS[r * D + c]; s1 += x; s2 += x * x; }
        #pragma unroll
        for (int o = 16; o; o >>= 1) {
            s1 += __shfl_xor_sync(0xFFFFFFFFu, s1, o);
            s2 += __shfl_xor_sync(0xFFFFFFFFu, s2, o);
        }
        if (lane == 0) {
            float mu = s1 * (1.f / D);
            float var = s2 * (1.f / D) - mu * mu;
            red[0][r] = mu;
            red[1][r] = rsqrtf(var + 1e-5f);
        }
    }
    __syncthreads();

    float ga = gamma[j], be = beta[j];
    for (int r = 0; r < nvld; r++) {
        float v = (acc[r] - red[0][r]) * red[1][r] * ga + be;
        v = fmaxf(v, 0.f);
        atomicAdd(&g_gsum[sb[r] * D + j], v);
    }
    if (j < nvld) atomicAdd(&g_gcnt[sb[j]], 1.f);
}

// ---------------- final: divide pooled sums ----------------
__global__ __launch_bounds__(D) void k_final(float* __restrict__ out, int G) {
    int g = blockIdx.x, j = threadIdx.x;
    out[g * D + j] = g_gsum[g * D + j] / fmaxf(g_gcnt[g], 1.f);
}

// ---------------- launch ----------------
extern "C" void kernel_launch(void* const* d_in, const int* in_sizes, int n_in,
                              void* d_out, int out_size) {
    const float* node_s = (const float*)d_in[0];
    const float* node_v = (const float*)d_in[1];
    const float* edge_s = (const float*)d_in[2];
    const int*   edge_index = (const int*)d_in[3];
    const int*   batch  = (const int*)d_in[4];
    const float* Ws  = (const float*)d_in[5];
    const float* bs  = (const float*)d_in[6];
    const float* Wv  = (const float*)d_in[7];
    const float* bv  = (const float*)d_in[8];
    const float* We  = (const float*)d_in[9];
    const float* be  = (const float*)d_in[10];
    const float* Wm1 = (const float*)d_in[11];
    const float* bm1 = (const float*)d_in[12];
    const float* Wm2 = (const float*)d_in[13];
    const float* bm2 = (const float*)d_in[14];
    const float* Wn  = (const float*)d_in[15];
    const float* bn  = (const float*)d_in[16];
    const float* gamma = (const float*)d_in[17];
    const float* beta  = (const float*)d_in[18];

    int N = in_sizes[0] / 23;
    int E = in_sizes[2] / 17;
    int G = out_size / D;
    int nb = (N + SCB - 1) / SCB;

    k_zero<<<256, 256>>>(N, G);
    k_hist<<<(E + 255) / 256, 256>>>(edge_index, E);
    k_folds<<<42 + D + 24, D>>>(We, be, Wm1, Ws, bs, bm1, Wm2, bm2, Wn, bn);
    k_scanA<<<nb, SCB>>>(N);
    k_scanB<<<1, 64>>>(nb, N);
    k_scanC<<<nb, SCB>>>(N);
    k_scatter<<<(E + 255) / 256, 256>>>(edge_index, edge_s, E);
    k_nodeEmb<<<(N + TM - 1) / TM, D>>>(node_s, node_v, Wv, bv, Wm1, N);
    k_edgeCSR<<<(N + TM - 1) / TM, D>>>(N);
    k_node2<<<(N + TM - 1) / TM, D>>>(node_s, Wn, gamma, beta, batch, N);
    k_final<<<G, D>>>((float*)d_out, G);
}

// round 13
// speedup vs baseline: 1.8147x; 1.1255x over previous
#include <cuda_runtime.h>
#include <cuda_bf16.h>
#include <math.h>

#define D 256
#define VD 16
#define TM 32          // rows (nodes) per CTA
#define TPAD 36        // padded row length for transposed SMEM tiles (144B, 16B-aligned)
#define CH 128         // edges per shared chunk in edge kernel
#define PF 4           // Qs prefetch depth
#define MAXN 50000
#define MAXE 400000
#define MAXG 256
#define SCB 1024       // scan block size
#define MAXSB ((MAXN + SCB - 1) / SCB)

typedef unsigned long long ull;

// ---- packed f32x2 helpers (sm_103a) ----
__device__ __forceinline__ ull pk2(float lo, float hi) {
    ull r; asm("mov.b64 %0, {%1,%2};" : "=l"(r) : "f"(lo), "f"(hi)); return r;
}
__device__ __forceinline__ ull fma2(ull a, ull b, ull c) {
    ull d; asm("fma.rn.f32x2 %0, %1, %2, %3;" : "=l"(d) : "l"(a), "l"(b), "l"(c)); return d;
}
__device__ __forceinline__ ull add2(ull a, ull b) {
    ull d; asm("add.rn.f32x2 %0, %1, %2;" : "=l"(d) : "l"(a), "l"(b)); return d;
}
__device__ __forceinline__ float2 upk(ull v) {
    float2 f; asm("mov.b64 {%0,%1}, %2;" : "=f"(f.x), "=f"(f.y) : "l"(v)); return f;
}

// ---------------- scratch ----------------
__device__ float g_vn  [MAXN * VD];
__device__ float g_Pd  [MAXN * D];
__device__ float g_Qs  [MAXN * D];
__device__ float g_agg [MAXN * D];
__device__ float g_WeF [17 * D];
__device__ float g_beF [D];
__device__ float g_AP  [23 * D];
__device__ float g_AQ  [23 * D];
__device__ float g_bP  [D];
__device__ float g_bQ  [D];
__device__ float g_AH  [23 * D];
__device__ float g_WmF [D * D];
__device__ float g_bH  [D];
__device__ float g_gsum[MAXG * D];
__device__ float g_gcnt[MAXG];
// CSR sort scratch
__device__ int   g_rowcnt[MAXN];
__device__ int   g_roff  [MAXN + 1];
__device__ int   g_cursor[MAXN];
__device__ int   g_bsum  [MAXSB];
__device__ int   g_boff  [MAXSB];
__device__ int   g_esrc  [MAXE];
__device__ int   g_erow  [MAXE];
__device__ float g_es    [MAXE * 20];

// ---------------- zero small accumulated buffers ----------------
__global__ void k_zero(int N, int G) {
    int i = blockIdx.x * blockDim.x + threadIdx.x;
    int gd = G * D;
    int total = gd + G + N;
    for (; i < total; i += gridDim.x * blockDim.x) {
        if (i < gd)           g_gsum[i] = 0.f;
        else if (i < gd + G)  g_gcnt[i - gd] = 0.f;
        else                  g_rowcnt[i - gd - G] = 0;
    }
}

// ---------------- histogram of dst ----------------
__global__ void k_hist(const int* __restrict__ edge_index, int E) {
    int i = blockIdx.x * blockDim.x + threadIdx.x;
    if (i < E) atomicAdd(&g_rowcnt[edge_index[E + i]], 1);
}

// ---------------- multi-block scan, phase A ----------------
__global__ __launch_bounds__(SCB) void k_scanA(int N) {
    __shared__ int wsum[32];
    int tid = threadIdx.x, lane = tid & 31, wid = tid >> 5;
    int idx = blockIdx.x * SCB + tid;
    int v = (idx < N) ? g_rowcnt[idx] : 0;
    int inc = v;
    #pragma unroll
    for (int o = 1; o < 32; o <<= 1) {
        int t = __shfl_up_sync(0xFFFFFFFFu, inc, o);
        if (lane >= o) inc += t;
    }
    if (lane == 31) wsum[wid] = inc;
    __syncthreads();
    if (wid == 0) {
        int s = wsum[lane];
        #pragma unroll
        for (int o = 1; o < 32; o <<= 1) {
            int t = __shfl_up_sync(0xFFFFFFFFu, s, o);
            if (lane >= o) s += t;
        }
        wsum[lane] = s;
    }
    __syncthreads();
    int excl = (wid ? wsum[wid - 1] : 0) + inc - v;
    if (idx < N) g_roff[idx] = excl;
    if (tid == SCB - 1) g_bsum[blockIdx.x] = excl + v;
}

// ---------------- phase B ----------------
__global__ __launch_bounds__(64) void k_scanB(int nb, int N) {
    __shared__ int sh[MAXSB];
    int tid = threadIdx.x;
    for (int i = tid; i < nb; i += 64) sh[i] = g_bsum[i];
    __syncthreads();
    if (tid == 0) {
        int run = 0;
        for (int i = 0; i < nb; i++) { int t = sh[i]; sh[i] = run; run += t; }
        g_roff[N] = run;
    }
    __syncthreads();
    for (int i = tid; i < nb; i += 64) g_boff[i] = sh[i];
}

// ---------------- phase C ----------------
__global__ __launch_bounds__(SCB) void k_scanC(int N) {
    int idx = blockIdx.x * SCB + threadIdx.x;
    if (idx < N) {
        int v = g_roff[idx] + g_boff[blockIdx.x];
        g_roff[idx] = v;
        g_cursor[idx] = v;
    }
}

// ---------------- scatter edges into sorted (by dst) arrays ----------------
__global__ void k_scatter(const int* __restrict__ edge_index,
                          const float* __restrict__ edge_s, int E) {
    int e = blockIdx.x * blockDim.x + threadIdx.x;
    if (e >= E) return;
    int src = edge_index[e];
    int dst = edge_index[E + e];
    int pos = atomicAdd(&g_cursor[dst], 1);
    g_esrc[pos] = src;
    g_erow[pos] = dst;
    const float* es = edge_s + (long long)e * 17;
    float v[17];
    #pragma unroll
    for (int k = 0; k < 17; k++) v[k] = es[k];
    float4* dst4 = (float4*)&g_es[(long long)pos * 20];
    dst4[0] = make_float4(v[0], v[1], v[2], v[3]);
    dst4[1] = make_float4(v[4], v[5], v[6], v[7]);
    dst4[2] = make_float4(v[8], v[9], v[10], v[11]);
    dst4[3] = make_float4(v[12], v[13], v[14], v[15]);
    g_es[(long long)pos * 20 + 16] = v[16];
}

// ---------------- merged folds: wef (18) | fold2 (24) | fold3 (280) ----------------
__global__ __launch_bounds__(D) void k_folds(const float* __restrict__ We,
                                             const float* __restrict__ be,
                                             const float* __restrict__ Wm1,
                                             const float* __restrict__ Ws,
                                             const float* __restrict__ bs,
                                             const float* __restrict__ bm1,
                                             const float* __restrict__ Wm2,
                                             const float* __restrict__ bm2,
                                             const float* __restrict__ Wn,
                                             const float* __restrict__ bn) {
    __shared__ float row[D];
    int j = threadIdx.x, bb = blockIdx.x;
    if (bb < 18) {
        int b = bb;
        row[j] = (b < 17) ? We[b * D + j] : be[j];
        __syncthreads();
        float a0 = 0.f, a1 = 0.f, a2 = 0.f, a3 = 0.f;
        #pragma unroll 8
        for (int c = 0; c < D; c += 4) {
            a0 += row[c + 0] * Wm1[(528 + c + 0) * D + j];
            a1 += row[c + 1] * Wm1[(528 + c + 1) * D + j];
            a2 += row[c + 2] * Wm1[(528 + c + 2) * D + j];
            a3 += row[c + 3] * Wm1[(528 + c + 3) * D + j];
        }
        float a = (a0 + a1) + (a2 + a3);
        if (b < 17) g_WeF[b * D + j] = a;
        else        g_beF[j] = a;
    } else if (bb < 42) {
        int b = bb - 18;
        row[j] = (b < 23) ? Ws[b * D + j] : bs[j];
        __syncthreads();
        float p0 = 0.f, p1 = 0.f, q0 = 0.f, q1 = 0.f;
        #pragma unroll 8
        for (int c = 0; c < D; c += 2) {
            float r0 = row[c], r1 = row[c + 1];
            p0 += r0 * Wm1[(c + 0) * D + j];
            p1 += r1 * Wm1[(c + 1) * D + j];
            q0 += r0 * Wm1[(D + c + 0) * D + j];
            q1 += r1 * Wm1[(D + c + 1) * D + j];
        }
        float aP = p0 + p1, aQ = q0 + q1;
        if (b < 23) { g_AP[b * D + j] = aP; g_AQ[b * D + j] = aQ; }
        else        { g_bP[j] = aP + bm1[j]; g_bQ[j] = aQ; }
    } else {
        int b = bb - 42;
        if (b < D)            row[j] = Wm2[b * D + j];
        else if (b < D + 23)  row[j] = Ws[(b - D) * D + j];
        else                  row[j] = bs[j] + bm2[j];
        __syncthreads();
        float a0 = 0.f, a1 = 0.f, a2 = 0.f, a3 = 0.f;
        #pragma unroll 8
        for (int c = 0; c < D; c += 4) {
            a0 += row[c + 0] * Wn[(c + 0) * D + j];
            a1 += row[c + 1] * Wn[(c + 1) * D + j];
            a2 += row[c + 2] * Wn[(c + 2) * D + j];
            a3 += row[c + 3] * Wn[(c + 3) * D + j];
        }
        float a = (a0 + a1) + (a2 + a3);
        if (b < D)            g_WmF[b * D + j] = a;
        else if (b < D + 23)  g_AH[(b - D) * D + j] = a;
        else                  g_bH[j] = a + bn[j];
    }
}

// ---------------- node embed + first-layer precompute (f32x2) ----------------
__global__ __launch_bounds__(D) void k_nodeEmb(const float* __restrict__ node_s,
                                               const float* __restrict__ node_v,
                                               const float* __restrict__ Wv,
                                               const float* __restrict__ bv,
                                               const float* __restrict__ Wm1,
                                               int N) {
    __shared__ __align__(16) float nsT[23][TM];
    __shared__ float nv[TM][12];
    __shared__ __align__(16) float vnT[VD][TM + 4];
    __shared__ float sWv[4 * VD];
    __shared__ float sbv[VD];
    int j = threadIdx.x;
    int n0 = blockIdx.x * TM;
    int nvld = min(TM, N - n0);

    for (int i = j; i < TM * 23; i += D) {
        int r = i / 23, k = i % 23;
        nsT[k][r] = (r < nvld) ? node_s[(n0 + r) * 23 + k] : 0.f;
    }
    for (int i = j; i < nvld * 12; i += D) nv[i / 12][i % 12] = node_v[n0 * 12 + i];
    if (j < 4 * VD) sWv[j] = Wv[j];
    if (j < VD) sbv[j] = bv[j];
    __syncthreads();

    for (int idx = j; idx < TM * VD; idx += D) {
        int r = idx / VD, o = idx % VD;
        float val = 0.f;
        if (r < nvld) {
            float x = sbv[o], y = sbv[o], z = sbv[o];
            #pragma unroll
            for (int k = 0; k < 4; k++) {
                float w = sWv[k * VD + o];
                x += nv[r][k * 3 + 0] * w;
                y += nv[r][k * 3 + 1] * w;
                z += nv[r][k * 3 + 2] * w;
            }
            val = sqrtf(x * x + y * y + z * z);
            g_vn[(n0 + r) * VD + o] = val;
        }
        vnT[o][r] = val;
    }
    __syncthreads();

    ull accP2[TM / 2], accQ2[TM / 2];
    {
        ull bp2 = pk2(g_bP[j], g_bP[j]);
        ull bq2 = pk2(g_bQ[j], g_bQ[j]);
        #pragma unroll
        for (int r = 0; r < TM / 2; r++) { accP2[r] = bp2; accQ2[r] = bq2; }
    }

    #pragma unroll 4
    for (int k = 0; k < 23; k++) {
        float wP = __ldg(&g_AP[k * D + j]);
        float wQ = __ldg(&g_AQ[k * D + j]);
        ull wP2 = pk2(wP, wP), wQ2 = pk2(wQ, wQ);
        const ull* rowp = (const ull*)&nsT[k][0];
        #pragma unroll
        for (int r = 0; r < TM / 2; r++) {
            ull a = rowp[r];
            accP2[r] = fma2(a, wP2, accP2[r]);
            accQ2[r] = fma2(a, wQ2, accQ2[r]);
        }
    }
    const float* W1V = Wm1 + 512 * D;
    #pragma unroll 4
    for (int k = 0; k < VD; k++) {
        float wV = __ldg(&W1V[k * D + j]);
        ull wV2 = pk2(wV, wV);
        const ull* rowp = (const ull*)&vnT[k][0];
        #pragma unroll
        for (int r = 0; r < TM / 2; r++) accQ2[r] = fma2(rowp[r], wV2, accQ2[r]);
    }
    for (int r2 = 0; r2 < TM / 2; r2++) {
        float2 p = upk(accP2[r2]), q = upk(accQ2[r2]);
        int r = 2 * r2;
        if (r < nvld)     { g_Pd[(n0 + r) * D + j] = p.x;     g_Qs[(n0 + r) * D + j] = q.x; }
        if (r + 1 < nvld) { g_Pd[(n0 + r + 1) * D + j] = p.y; g_Qs[(n0 + r + 1) * D + j] = q.y; }
    }
}

// ---------------- edge kernel (CSR, f32x2 dot, PF-deep Qs prefetch) ----------------
__global__ __launch_bounds__(D) void k_edgeCSR(int N) {
    __shared__ float sPd[TM * D];
    __shared__ __align__(16) float sEs[CH][20];
    __shared__ int   sSrc[CH];
    __shared__ int   sRow[CH];
    int j = threadIdx.x;
    int n0 = blockIdx.x * TM;
    int nvld = min(TM, N - n0);

    for (int i = j; i < nvld * D; i += D) {
        int r = i >> 8, k = i & 255;
        sPd[r * D + k] = g_Pd[(n0 + r) * D + k];
    }
    int e0 = g_roff[n0];
    int e1 = g_roff[n0 + nvld];

    ull w2[8];
    float wf16;
    {
        float wf[17];
        #pragma unroll
        for (int k = 0; k < 17; k++) wf[k] = g_WeF[k * D + j];
        #pragma unroll
        for (int k = 0; k < 8; k++) w2[k] = pk2(wf[2 * k], wf[2 * k + 1]);
        wf16 = wf[16];
    }
    float bef = g_beF[j];

    int cur = -1;
    float a = 0.f, bpd = 0.f;

    for (int base = e0; base < e1; base += CH) {
        int cnt = min(CH, e1 - base);
        __syncthreads();
        for (int t = j; t < cnt * 20; t += D)
            sEs[t / 20][t % 20] = g_es[(long long)base * 20 + t];
        for (int t = j; t < cnt; t += D) {
            sSrc[t] = g_esrc[base + t];
            sRow[t] = g_erow[base + t] - n0;
        }
        __syncthreads();

        float q[PF];
        #pragma unroll
        for (int p = 0; p < PF; p++)
            q[p] = (p < cnt) ? __ldg(&g_Qs[sSrc[p] * D + j]) : 0.f;

        for (int i = 0; i < cnt; i += PF) {
            #pragma unroll
            for (int u = 0; u < PF; u++) {
                int idx = i + u;
                if (idx >= cnt) break;
                float qc = q[u];
                int nidx = idx + PF;
                q[u] = (nidx < cnt) ? __ldg(&g_Qs[sSrc[nidx] * D + j]) : 0.f;
                int r = sRow[idx];
                if (r != cur) {
                    if (cur >= 0) g_agg[(n0 + cur) * D + j] = a;
                    cur = r; a = 0.f;
                    bpd = bef + sPd[r * D + j];
                }
                const ulonglong2* ep = (const ulonglong2*)sEs[idx];
                ulonglong2 p0 = ep[0], p1 = ep[1];
                ull ha = pk2(bpd + qc, sEs[idx][16] * wf16);
                ull hb = pk2(0.f, 0.f);
                ha = fma2(p0.x, w2[0], ha);
                hb = fma2(p0.y, w2[1], hb);
                ha = fma2(p1.x, w2[2], ha);
                hb = fma2(p1.y, w2[3], hb);
                ulonglong2 p2 = ep[2], p3 = ep[3];
                ha = fma2(p2.x, w2[4], ha);
                hb = fma2(p2.y, w2[5], hb);
                ha = fma2(p3.x, w2[6], ha);
                hb = fma2(p3.y, w2[7], hb);
                float2 hf = upk(add2(ha, hb));
                a += fmaxf(hf.x + hf.y, 0.f);
            }
        }
    }
    if (cur >= 0) g_agg[(n0 + cur) * D + j] = a;
}

// ---------------- node output: 4col x 8row register-tiled GEMM + LN + pooling ----------------
__global__ __launch_bounds__(D) void k_node2(const float* __restrict__ node_s,
                                             const float* __restrict__ Wn,
                                             const float* __restrict__ gamma,
                                             const float* __restrict__ beta,
                                             const int* __restrict__ batch,
                                             int N) {
    __shared__ __align__(16) float aT[D * TPAD];
    __shared__ __align__(16) float ns2T[23][TM];
    __shared__ __align__(16) float vnT[VD][TPAD];
    __shared__ float rc[TM];
    __shared__ float red[2][TM];
    __shared__ int sb[TM];
    int j = threadIdx.x;
    int n0 = blockIdx.x * TM;
    int nvld = min(TM, N - n0);

    // thread tile: 4 cols x 8 rows
    int c0 = (j & 63) * 4;
    int r0 = (j >> 6) * 8;

    if (j < TM) {
        float deg = 0.f;
        if (j < nvld) {
            int n = n0 + j;
            deg = (float)(g_roff[n + 1] - g_roff[n]);
            sb[j] = batch[n];
        } else sb[j] = 0;
        rc[j] = 1.f / fmaxf(deg, 1.f);
    }
    for (int i = j; i < TM * 23; i += D) {
        int r = i / 23, k = i % 23;
        ns2T[k][r] = (r < nvld) ? node_s[(n0 + r) * 23 + k] : 0.f;
    }
    for (int i = j; i < TM * VD; i += D) {
        int r = i / VD, k = i % VD;
        vnT[k][r] = (r < nvld) ? g_vn[(n0 + r) * VD + k] : 0.f;
    }
    __syncthreads();
    for (int i = j; i < TM * D; i += D) {
        int r = i >> 8, k = i & 255;
        aT[k * TPAD + r] = (r < nvld) ? g_agg[(n0 + r) * D + k] * rc[r] : 0.f;
    }
    __syncthreads();

    // acc2[cc][pp]: col cc, row-pair pp (rows r0+2pp, r0+2pp+1)
    ull acc2[4][4];
    {
        float4 b4 = *(const float4*)&g_bH[c0];
        #pragma unroll
        for (int pp = 0; pp < 4; pp++) {
            acc2[0][pp] = pk2(b4.x, b4.x);
            acc2[1][pp] = pk2(b4.y, b4.y);
            acc2[2][pp] = pk2(b4.z, b4.z);
            acc2[3][pp] = pk2(b4.w, b4.w);
        }
    }

    #pragma unroll 4
    for (int k = 0; k < 23; k++) {
        float4 w = __ldg((const float4*)&g_AH[k * D + c0]);
        ull d0 = pk2(w.x, w.x), d1 = pk2(w.y, w.y), d2 = pk2(w.z, w.z), d3 = pk2(w.w, w.w);
        const ull* rp = (const ull*)&ns2T[k][r0];
        #pragma unroll
        for (int pp = 0; pp < 4; pp++) {
            ull a = rp[pp];
            acc2[0][pp] = fma2(a, d0, acc2[0][pp]);
            acc2[1][pp] = fma2(a, d1, acc2[1][pp]);
            acc2[2][pp] = fma2(a, d2, acc2[2][pp]);
            acc2[3][pp] = fma2(a, d3, acc2[3][pp]);
        }
    }
    const float* WnV = Wn + D * D;
    #pragma unroll 4
    for (int k = 0; k < VD; k++) {
        float4 w = __ldg((const float4*)&WnV[k * D + c0]);
        ull d0 = pk2(w.x, w.x), d1 = pk2(w.y, w.y), d2 = pk2(w.z, w.z), d3 = pk2(w.w, w.w);
        const ull* rp = (const ull*)&vnT[k][r0];
        #pragma unroll
        for (int pp = 0; pp < 4; pp++) {
            ull a = rp[pp];
            acc2[0][pp] = fma2(a, d0, acc2[0][pp]);
            acc2[1][pp] = fma2(a, d1, acc2[1][pp]);
            acc2[2][pp] = fma2(a, d2, acc2[2][pp]);
            acc2[3][pp] = fma2(a, d3, acc2[3][pp]);
        }
    }
    // main 256-K GEMM over g_WmF, LDG.128 weights with prefetch
    {
        float4 w = __ldg((const float4*)&g_WmF[c0]);
        #pragma unroll 4
        for (int k = 0; k < D; k++) {
            float4 cw = w;
            if (k + 1 < D) w = __ldg((const float4*)&g_WmF[(k + 1) * D + c0]);
            ull d0 = pk2(cw.x, cw.x), d1 = pk2(cw.y, cw.y), d2 = pk2(cw.z, cw.z), d3 = pk2(cw.w, cw.w);
            const ull* rp = (const ull*)&aT[k * TPAD + r0];
            ull a0 = rp[0], a1 = rp[1], a2 = rp[2], a3 = rp[3];
            acc2[0][0] = fma2(a0, d0, acc2[0][0]);
            acc2[1][0] = fma2(a0, d1, acc2[1][0]);
            acc2[2][0] = fma2(a0, d2, acc2[2][0]);
            acc2[3][0] = fma2(a0, d3, acc2[3][0]);
            acc2[0][1] = fma2(a1, d0, acc2[0][1]);
            acc2[1][1] = fma2(a1, d1, acc2[1][1]);
            acc2[2][1] = fma2(a1, d2, acc2[2][1]);
            acc2[3][1] = fma2(a1, d3, acc2[3][1]);
            acc2[0][2] = fma2(a2, d0, acc2[0][2]);
            acc2[1][2] = fma2(a2, d1, acc2[1][2]);
            acc2[2][2] = fma2(a2, d2, acc2[2][2]);
            acc2[3][2] = fma2(a2, d3, acc2[3][2]);
            acc2[0][3] = fma2(a3, d0, acc2[0][3]);
            acc2[1][3] = fma2(a3, d1, acc2[1][3]);
            acc2[2][3] = fma2(a3, d2, acc2[2][3]);
            acc2[3][3] = fma2(a3, d3, acc2[3][3]);
        }
    }
    __syncthreads();                 // done reading aT; reuse as h [TM][D]
    float* hS = aT;
    #pragma unroll
    for (int pp = 0; pp < 4; pp++) {
        float2 f0 = upk(acc2[0][pp]), f1 = upk(acc2[1][pp]);
        float2 f2 = upk(acc2[2][pp]), f3 = upk(acc2[3][pp]);
        *(float4*)&hS[(r0 + 2 * pp) * D + c0]     = make_float4(f0.x, f1.x, f2.x, f3.x);
        *(float4*)&hS[(r0 + 2 * pp + 1) * D + c0] = make_float4(f0.y, f1.y, f2.y, f3.y);
    }
    __syncthreads();

    int wid = j >> 5, lane = j & 31;
    for (int r = wid; r < TM; r += 8) {
        float s1 = 0.f, s2 = 0.f;
        #pragma unroll
        for (int c = lane; c < D; c += 32) { float x = hS[r * D + c]; s1 += x; s2 += x * x; }
        #pragma unroll
        for (int o = 16; o; o >>= 1) {
            s1 += __shfl_xor_sync(0xFFFFFFFFu, s1, o);
            s2 += __shfl_xor_sync(0xFFFFFFFFu, s2, o);
        }
        if (lane == 0) {
            float mu = s1 * (1.f / D);
            float var = s2 * (1.f / D) - mu * mu;
            red[0][r] = mu;
            red[1][r] = rsqrtf(var + 1e-5f);
        }
    }
    __syncthreads();

    float4 ga = *(const float4*)&gamma[c0];
    float4 be = *(const float4*)&beta[c0];
    #pragma unroll
    for (int pp = 0; pp < 4; pp++) {
        float2 f0 = upk(acc2[0][pp]), f1 = upk(acc2[1][pp]);
        float2 f2 = upk(acc2[2][pp]), f3 = upk(acc2[3][pp]);
        int ra = r0 + 2 * pp, rb = ra + 1;
        if (ra < nvld) {
            float mu = red[0][ra], rs = red[1][ra];
            float* gs = &g_gsum[sb[ra] * D + c0];
            atomicAdd(gs + 0, fmaxf((f0.x - mu) * rs * ga.x + be.x, 0.f));
            atomicAdd(gs + 1, fmaxf((f1.x - mu) * rs * ga.y + be.y, 0.f));
            atomicAdd(gs + 2, fmaxf((f2.x - mu) * rs * ga.z + be.z, 0.f));
            atomicAdd(gs + 3, fmaxf((f3.x - mu) * rs * ga.w + be.w, 0.f));
        }
        if (rb < nvld) {
            float mu = red[0][rb], rs = red[1][rb];
            float* gs = &g_gsum[sb[rb] * D + c0];
            atomicAdd(gs + 0, fmaxf((f0.y - mu) * rs * ga.x + be.x, 0.f));
            atomicAdd(gs + 1, fmaxf((f1.y - mu) * rs * ga.y + be.y, 0.f));
            atomicAdd(gs + 2, fmaxf((f2.y - mu) * rs * ga.z + be.z, 0.f));
            atomicAdd(gs + 3, fmaxf((f3.y - mu) * rs * ga.w + be.w, 0.f));
        }
    }
    if (j < nvld) atomicAdd(&g_gcnt[sb[j]], 1.f);
}

// ---------------- final: divide pooled sums ----------------
__global__ __launch_bounds__(D) void k_final(float* __restrict__ out, int G) {
    int g = blockIdx.x, j = threadIdx.x;
    out[g * D + j] = g_gsum[g * D + j] / fmaxf(g_gcnt[g], 1.f);
}

// ---------------- launch ----------------
extern "C" void kernel_launch(void* const* d_in, const int* in_sizes, int n_in,
                              void* d_out, int out_size) {
    const float* node_s = (const float*)d_in[0];
    const float* node_v = (const float*)d_in[1];
    const float* edge_s = (const float*)d_in[2];
    const int*   edge_index = (const int*)d_in[3];
    const int*   batch  = (const int*)d_in[4];
    const float* Ws  = (const float*)d_in[5];
    const float* bs  = (const float*)d_in[6];
    const float* Wv  = (const float*)d_in[7];
    const float* bv  = (const float*)d_in[8];
    const float* We  = (const float*)d_in[9];
    const float* be  = (const float*)d_in[10];
    const float* Wm1 = (const float*)d_in[11];
    const float* bm1 = (const float*)d_in[12];
    const float* Wm2 = (const float*)d_in[13];
    const float* bm2 = (const float*)d_in[14];
    const float* Wn  = (const float*)d_in[15];
    const float* bn  = (const float*)d_in[16];
    const float* gamma = (const float*)d_in[17];
    const float* beta  = (const float*)d_in[18];

    int N = in_sizes[0] / 23;
    int E = in_sizes[2] / 17;
    int G = out_size / D;
    int nb = (N + SCB - 1) / SCB;

    k_zero<<<256, 256>>>(N, G);
    k_hist<<<(E + 255) / 256, 256>>>(edge_index, E);
    k_folds<<<42 + D + 24, D>>>(We, be, Wm1, Ws, bs, bm1, Wm2, bm2, Wn, bn);
    k_scanA<<<nb, SCB>>>(N);
    k_scanB<<<1, 64>>>(nb, N);
    k_scanC<<<nb, SCB>>>(N);
    k_scatter<<<(E + 255) / 256, 256>>>(edge_index, edge_s, E);
    k_nodeEmb<<<(N + TM - 1) / TM, D>>>(node_s, node_v, Wv, bv, Wm1, N);
    k_edgeCSR<<<(N + TM - 1) / TM, D>>>(N);
    k_node2<<<(N + TM - 1) / TM, D>>>(node_s, Wn, gamma, beta, batch, N);
    k_final<<<G, D>>>((float*)d_out, G);
}